// round 3
// baseline (speedup 1.0000x reference)
#include <cuda_runtime.h>

#define N_NODES 50000
#define N_EDGES 800000
#define CH 128          // HEADS*OUT_CH = 4*32
#define NEG_SLOPE 0.2f

// ---------------- scratch (static device memory; no runtime allocs) ----------
__device__ __align__(16) float g_xl[N_NODES * CH];   // target projection
__device__ __align__(16) float g_xr[N_NODES * CH];   // source projection
__device__ int g_cnt[N_NODES];
__device__ int g_cur[N_NODES];
__device__ int g_off[N_NODES + 1];
__device__ int g_esrc[N_EDGES];

// ---------------- packed f32x2 helpers (FFMA2 — 2x fp32 rate on sm_103a) -----
__device__ __forceinline__ void fma2(unsigned long long& d,
                                     unsigned long long a,
                                     unsigned long long b) {
    asm("fma.rn.f32x2 %0, %1, %2, %0;" : "+l"(d) : "l"(a), "l"(b));
}
__device__ __forceinline__ unsigned long long dup2(float x) {
    unsigned long long r;
    asm("mov.b64 %0, {%1, %1};" : "=l"(r) : "f"(x));
    return r;
}
__device__ __forceinline__ float2 unpack2(unsigned long long v) {
    float2 r;
    asm("mov.b64 {%0, %1}, %2;" : "=f"(r.x), "=f"(r.y) : "l"(v));
    return r;
}

// ---------------- fused dual projection GEMM (K-tiled, static smem) ----------
// C[n][o] = sum_k X[n][k] * W[o][k] + b[o];  blockIdx.y selects (Wl,bl,g_xl)
// vs (Wr,br,g_xr). Tile: 64 nodes x 128 outs; K processed in 4 tiles of 32.
// Per thread: 4 nodes x 8 outs, accumulated as 16 f32x2 pairs.
#define BM 64
#define KT 32
#define XLD (KT + 4)     // 36, keeps float4 alignment
#define WLD 132

__global__ __launch_bounds__(256)
void gemm_kernel(const float* __restrict__ X,
                 const float* __restrict__ Wl, const float* __restrict__ bl,
                 const float* __restrict__ Wr, const float* __restrict__ br) {
    __shared__ float Xs[BM * XLD];   // 9216 B
    __shared__ float Ws[KT * WLD];   // 16896 B  -> total ~25.5 KB static

    const float* W    = blockIdx.y ? Wr : Wl;
    const float* bias = blockIdx.y ? br : bl;
    float* dst        = blockIdx.y ? g_xr : g_xl;

    const int tid = threadIdx.x;
    const int nb  = blockIdx.x * BM;

    const int og = tid & 15;     // 16 output groups of 8
    const int ng = tid >> 4;     // 16 node groups of 4
    const int o0 = og << 3;
    const int n0 = ng << 2;

    unsigned long long acc[4][4];
#pragma unroll
    for (int i = 0; i < 4; i++)
#pragma unroll
        for (int j = 0; j < 4; j++) acc[i][j] = 0ull;

    for (int kt = 0; kt < CH; kt += KT) {
        // X tile: 64 rows x 32 cols -> 512 float4, 2 per thread, coalesced.
#pragma unroll
        for (int t = 0; t < 2; t++) {
            int idx = tid + t * 256;          // 0..511
            int n   = idx >> 3;
            int q   = (idx & 7) << 2;
            int gn  = nb + n;
            float4 v = make_float4(0.f, 0.f, 0.f, 0.f);
            if (gn < N_NODES) v = *(const float4*)(X + gn * CH + kt + q);
            *(float4*)(Xs + n * XLD + q) = v;
        }
        // W tile transposed: 128 rows x 32 cols -> Ws[k][o].
#pragma unroll
        for (int t = 0; t < 4; t++) {
            int idx = tid + t * 256;          // 0..1023
            int o   = idx >> 3;
            int q   = (idx & 7) << 2;
            float4 w = *(const float4*)(W + o * CH + kt + q);
            Ws[(q + 0) * WLD + o] = w.x;
            Ws[(q + 1) * WLD + o] = w.y;
            Ws[(q + 2) * WLD + o] = w.z;
            Ws[(q + 3) * WLD + o] = w.w;
        }
        __syncthreads();

#pragma unroll 8
        for (int k = 0; k < KT; k++) {
            const unsigned long long* wrow =
                (const unsigned long long*)(Ws + k * WLD + o0);
            unsigned long long w0 = wrow[0], w1 = wrow[1],
                               w2 = wrow[2], w3 = wrow[3];
            unsigned long long xd0 = dup2(Xs[(n0 + 0) * XLD + k]);
            unsigned long long xd1 = dup2(Xs[(n0 + 1) * XLD + k]);
            unsigned long long xd2 = dup2(Xs[(n0 + 2) * XLD + k]);
            unsigned long long xd3 = dup2(Xs[(n0 + 3) * XLD + k]);
            fma2(acc[0][0], w0, xd0); fma2(acc[0][1], w1, xd0);
            fma2(acc[0][2], w2, xd0); fma2(acc[0][3], w3, xd0);
            fma2(acc[1][0], w0, xd1); fma2(acc[1][1], w1, xd1);
            fma2(acc[1][2], w2, xd1); fma2(acc[1][3], w3, xd1);
            fma2(acc[2][0], w0, xd2); fma2(acc[2][1], w1, xd2);
            fma2(acc[2][2], w2, xd2); fma2(acc[2][3], w3, xd2);
            fma2(acc[3][0], w0, xd3); fma2(acc[3][1], w1, xd3);
            fma2(acc[3][2], w2, xd3); fma2(acc[3][3], w3, xd3);
        }
        __syncthreads();
    }

    const float2* bp = (const float2*)(bias + o0);
    float2 b0 = bp[0], b1 = bp[1], b2 = bp[2], b3 = bp[3];
#pragma unroll
    for (int i = 0; i < 4; i++) {
        int gn = nb + n0 + i;
        if (gn < N_NODES) {
            float2 r0 = unpack2(acc[i][0]);
            float2 r1 = unpack2(acc[i][1]);
            float2 r2 = unpack2(acc[i][2]);
            float2 r3 = unpack2(acc[i][3]);
            float4 lo = make_float4(r0.x + b0.x, r0.y + b0.y,
                                    r1.x + b1.x, r1.y + b1.y);
            float4 hi = make_float4(r2.x + b2.x, r2.y + b2.y,
                                    r3.x + b3.x, r3.y + b3.y);
            *(float4*)(dst + gn * CH + o0)     = lo;
            *(float4*)(dst + gn * CH + o0 + 4) = hi;
        }
    }
}

// ---------------- CSR build --------------------------------------------------
// edge_index is int32 (JAX x64 disabled), layout [2][N_EDGES]: row0=src, row1=tgt.
__global__ void zero_kernel() {
    int i = blockIdx.x * blockDim.x + threadIdx.x;
    if (i < N_NODES) { g_cnt[i] = 0; g_cur[i] = 0; }
}

__global__ void count_kernel(const int* __restrict__ ei) {
    int e = blockIdx.x * blockDim.x + threadIdx.x;
    if (e < N_EDGES) {
        int t = ei[N_EDGES + e];   // tgt row
        atomicAdd(&g_cnt[t], 1);
    }
}

__global__ void scan_kernel() {
    __shared__ int sums[1024];
    const int tid = threadIdx.x;
    const int CHK = (N_NODES + 1023) / 1024;   // 49
    int base = tid * CHK;
    int s = 0;
    for (int j = 0; j < CHK; j++) {
        int idx = base + j;
        if (idx < N_NODES) s += g_cnt[idx];
    }
    sums[tid] = s;
    __syncthreads();
    for (int o = 1; o < 1024; o <<= 1) {
        int v = 0;
        if (tid >= o) v = sums[tid - o];
        __syncthreads();
        sums[tid] += v;
        __syncthreads();
    }
    int run = (tid == 0) ? 0 : sums[tid - 1];
    for (int j = 0; j < CHK; j++) {
        int idx = base + j;
        if (idx < N_NODES) { g_off[idx] = run; run += g_cnt[idx]; }
    }
    if (tid == 1023) g_off[N_NODES] = sums[1023];
}

__global__ void scatter_kernel(const int* __restrict__ ei) {
    int e = blockIdx.x * blockDim.x + threadIdx.x;
    if (e < N_EDGES) {
        int s = ei[e];
        int t = ei[N_EDGES + e];
        int pos = g_off[t] + atomicAdd(&g_cur[t], 1);
        g_esrc[pos] = s;
    }
}

// ---------------- warp-per-node online-softmax aggregation -------------------
// Channel c in [0,128); lane holds channels [4*lane, 4*lane+4) so lanes
// 8g..8g+7 form head g; per-head reductions via 3 shfl_xor steps (o=1,2,4).
__global__ __launch_bounds__(256)
void agg_kernel(const float* __restrict__ att,
                const float* __restrict__ bias,
                float* __restrict__ out) {
    int w    = (blockIdx.x * blockDim.x + threadIdx.x) >> 5;
    int lane = threadIdx.x & 31;
    if (w >= N_NODES) return;
    const int i  = w;
    const int c0 = lane << 2;

    const float4 xlv = *(const float4*)(g_xl + i * CH + c0);
    const float4 av  = *(const float4*)(att + c0);
    const float4 xrs = *(const float4*)(g_xr + i * CH + c0);

    // self-loop attention logit
    float s0 = xlv.x + xrs.x; s0 = s0 > 0.f ? s0 : NEG_SLOPE * s0;
    float s1 = xlv.y + xrs.y; s1 = s1 > 0.f ? s1 : NEG_SLOPE * s1;
    float s2 = xlv.z + xrs.z; s2 = s2 > 0.f ? s2 : NEG_SLOPE * s2;
    float s3 = xlv.w + xrs.w; s3 = s3 > 0.f ? s3 : NEG_SLOPE * s3;
    float p = av.x * s0 + av.y * s1 + av.z * s2 + av.w * s3;
#pragma unroll
    for (int o = 1; o < 8; o <<= 1) p += __shfl_xor_sync(0xffffffffu, p, o);

    float m = p;
    float d = 1.0f;
    float4 acc = xrs;

    const int beg = g_off[i];
    const int end = g_off[i + 1];
    for (int e = beg; e < end; e++) {
        int src = __ldg(&g_esrc[e]);
        float4 xv = *(const float4*)(g_xr + src * CH + c0);
        float t0 = xlv.x + xv.x; t0 = t0 > 0.f ? t0 : NEG_SLOPE * t0;
        float t1 = xlv.y + xv.y; t1 = t1 > 0.f ? t1 : NEG_SLOPE * t1;
        float t2 = xlv.z + xv.z; t2 = t2 > 0.f ? t2 : NEG_SLOPE * t2;
        float t3 = xlv.w + xv.w; t3 = t3 > 0.f ? t3 : NEG_SLOPE * t3;
        float q = av.x * t0 + av.y * t1 + av.z * t2 + av.w * t3;
#pragma unroll
        for (int o = 1; o < 8; o <<= 1) q += __shfl_xor_sync(0xffffffffu, q, o);

        float nm = fmaxf(m, q);
        float wm = __expf(m - nm);
        float wq = __expf(q - nm);
        d = d * wm + wq;
        acc.x = acc.x * wm + wq * xv.x;
        acc.y = acc.y * wm + wq * xv.y;
        acc.z = acc.z * wm + wq * xv.z;
        acc.w = acc.w * wm + wq * xv.w;
        m = nm;
    }

    float inv = 1.0f / d;
    const float4 bv = *(const float4*)(bias + c0);
    float4 r = make_float4(acc.x * inv + bv.x, acc.y * inv + bv.y,
                           acc.z * inv + bv.z, acc.w * inv + bv.w);
    *(float4*)(out + i * CH + c0) = r;
}

// ---------------- launch ------------------------------------------------------
extern "C" void kernel_launch(void* const* d_in, const int* in_sizes, int n_in,
                              void* d_out, int out_size) {
    const float* x    = (const float*)d_in[0];
    const int*   ei   = (const int*)d_in[1];     // int32! (JAX x64 disabled)
    const float* Wl   = (const float*)d_in[2];
    const float* bl   = (const float*)d_in[3];
    const float* Wr   = (const float*)d_in[4];
    const float* br   = (const float*)d_in[5];
    const float* att  = (const float*)d_in[6];
    const float* bias = (const float*)d_in[7];
    float*       out  = (float*)d_out;

    dim3 gg((N_NODES + BM - 1) / BM, 2);
    gemm_kernel<<<gg, 256>>>(x, Wl, bl, Wr, br);

    zero_kernel<<<(N_NODES + 255) / 256, 256>>>();
    count_kernel<<<(N_EDGES + 255) / 256, 256>>>(ei);
    scan_kernel<<<1, 1024>>>();
    scatter_kernel<<<(N_EDGES + 255) / 256, 256>>>(ei);

    agg_kernel<<<(N_NODES * 32 + 255) / 256, 256>>>(att, bias, out);
}

// round 5
// speedup vs baseline: 1.2090x; 1.2090x over previous
#include <cuda_runtime.h>

#define N_NODES 50000
#define N_EDGES 800000
#define CH 128          // HEADS*OUT_CH = 4*32
#define NEG_SLOPE 0.2f
#define SCAN_B 256
#define NB_SCAN ((N_NODES + SCAN_B - 1) / SCAN_B)   // 196

// ---------------- scratch (static device memory; zero-init at load) ----------
__device__ __align__(16) float g_xl[N_NODES * CH];   // target projection
__device__ __align__(16) float g_xr[N_NODES * CH];   // source projection
__device__ int g_cnt[N_NODES];        // zero-initialized; re-zeroed by scan3
__device__ int g_off[N_NODES + 1];
__device__ int g_esrc[N_EDGES];
__device__ int g_bsum[NB_SCAN];
__device__ int g_boff[NB_SCAN];

// ---------------- packed f32x2 helpers (FFMA2 — 2x fp32 rate on sm_103a) -----
__device__ __forceinline__ void fma2(unsigned long long& d,
                                     unsigned long long a,
                                     unsigned long long b) {
    asm("fma.rn.f32x2 %0, %1, %2, %0;" : "+l"(d) : "l"(a), "l"(b));
}
__device__ __forceinline__ unsigned long long dup2(float x) {
    unsigned long long r;
    asm("mov.b64 %0, {%1, %1};" : "=l"(r) : "f"(x));
    return r;
}
__device__ __forceinline__ float2 unpack2(unsigned long long v) {
    float2 r;
    asm("mov.b64 {%0, %1}, %2;" : "=f"(r.x), "=f"(r.y) : "l"(v));
    return r;
}

// ---------------- fused dual projection GEMM (K-tiled, static smem) ----------
#define BM 64
#define KT 32
#define XLD (KT + 4)
#define WLD 132

__global__ __launch_bounds__(256)
void gemm_kernel(const float* __restrict__ X,
                 const float* __restrict__ Wl, const float* __restrict__ bl,
                 const float* __restrict__ Wr, const float* __restrict__ br) {
    __shared__ float Xs[BM * XLD];
    __shared__ float Ws[KT * WLD];

    const float* W    = blockIdx.y ? Wr : Wl;
    const float* bias = blockIdx.y ? br : bl;
    float* dst        = blockIdx.y ? g_xr : g_xl;

    const int tid = threadIdx.x;
    const int nb  = blockIdx.x * BM;

    const int og = tid & 15;
    const int ng = tid >> 4;
    const int o0 = og << 3;
    const int n0 = ng << 2;

    unsigned long long acc[4][4];
#pragma unroll
    for (int i = 0; i < 4; i++)
#pragma unroll
        for (int j = 0; j < 4; j++) acc[i][j] = 0ull;

    for (int kt = 0; kt < CH; kt += KT) {
#pragma unroll
        for (int t = 0; t < 2; t++) {
            int idx = tid + t * 256;
            int n   = idx >> 3;
            int q   = (idx & 7) << 2;
            int gn  = nb + n;
            float4 v = make_float4(0.f, 0.f, 0.f, 0.f);
            if (gn < N_NODES) v = *(const float4*)(X + gn * CH + kt + q);
            *(float4*)(Xs + n * XLD + q) = v;
        }
#pragma unroll
        for (int t = 0; t < 4; t++) {
            int idx = tid + t * 256;
            int o   = idx >> 3;
            int q   = (idx & 7) << 2;
            float4 w = *(const float4*)(W + o * CH + kt + q);
            Ws[(q + 0) * WLD + o] = w.x;
            Ws[(q + 1) * WLD + o] = w.y;
            Ws[(q + 2) * WLD + o] = w.z;
            Ws[(q + 3) * WLD + o] = w.w;
        }
        __syncthreads();

#pragma unroll 8
        for (int k = 0; k < KT; k++) {
            const unsigned long long* wrow =
                (const unsigned long long*)(Ws + k * WLD + o0);
            unsigned long long w0 = wrow[0], w1 = wrow[1],
                               w2 = wrow[2], w3 = wrow[3];
            unsigned long long xd0 = dup2(Xs[(n0 + 0) * XLD + k]);
            unsigned long long xd1 = dup2(Xs[(n0 + 1) * XLD + k]);
            unsigned long long xd2 = dup2(Xs[(n0 + 2) * XLD + k]);
            unsigned long long xd3 = dup2(Xs[(n0 + 3) * XLD + k]);
            fma2(acc[0][0], w0, xd0); fma2(acc[0][1], w1, xd0);
            fma2(acc[0][2], w2, xd0); fma2(acc[0][3], w3, xd0);
            fma2(acc[1][0], w0, xd1); fma2(acc[1][1], w1, xd1);
            fma2(acc[1][2], w2, xd1); fma2(acc[1][3], w3, xd1);
            fma2(acc[2][0], w0, xd2); fma2(acc[2][1], w1, xd2);
            fma2(acc[2][2], w2, xd2); fma2(acc[2][3], w3, xd2);
            fma2(acc[3][0], w0, xd3); fma2(acc[3][1], w1, xd3);
            fma2(acc[3][2], w2, xd3); fma2(acc[3][3], w3, xd3);
        }
        __syncthreads();
    }

    const float2* bp = (const float2*)(bias + o0);
    float2 b0 = bp[0], b1 = bp[1], b2 = bp[2], b3 = bp[3];
#pragma unroll
    for (int i = 0; i < 4; i++) {
        int gn = nb + n0 + i;
        if (gn < N_NODES) {
            float2 r0 = unpack2(acc[i][0]);
            float2 r1 = unpack2(acc[i][1]);
            float2 r2 = unpack2(acc[i][2]);
            float2 r3 = unpack2(acc[i][3]);
            float4 lo = make_float4(r0.x + b0.x, r0.y + b0.y,
                                    r1.x + b1.x, r1.y + b1.y);
            float4 hi = make_float4(r2.x + b2.x, r2.y + b2.y,
                                    r3.x + b3.x, r3.y + b3.y);
            *(float4*)(dst + gn * CH + o0)     = lo;
            *(float4*)(dst + gn * CH + o0 + 4) = hi;
        }
    }
}

// ---------------- CSR build --------------------------------------------------
// edge_index is int32, layout [2][N_EDGES]: row0 = src, row1 = tgt.
__global__ void count_kernel(const int* __restrict__ ei) {
    int e = blockIdx.x * blockDim.x + threadIdx.x;
    if (e < N_EDGES) atomicAdd(&g_cnt[ei[N_EDGES + e]], 1);
}

// scan phase 1: per-block sums of g_cnt
__global__ __launch_bounds__(SCAN_B)
void scan1_kernel() {
    __shared__ int ws[SCAN_B / 32];
    int idx  = blockIdx.x * SCAN_B + threadIdx.x;
    int v    = (idx < N_NODES) ? g_cnt[idx] : 0;
#pragma unroll
    for (int o = 16; o > 0; o >>= 1) v += __shfl_xor_sync(0xffffffffu, v, o);
    if ((threadIdx.x & 31) == 0) ws[threadIdx.x >> 5] = v;
    __syncthreads();
    if (threadIdx.x < 32) {                 // WHOLE warp 0 executes the shfls
        int s = (threadIdx.x < SCAN_B / 32) ? ws[threadIdx.x] : 0;
#pragma unroll
        for (int o = SCAN_B / 64; o > 0; o >>= 1)
            s += __shfl_xor_sync(0xffffffffu, s, o, SCAN_B / 32);
        if (threadIdx.x == 0) g_bsum[blockIdx.x] = s;
    }
}

// scan phase 2: exclusive scan of NB_SCAN block sums (single block)
__global__ __launch_bounds__(256)
void scan2_kernel() {
    __shared__ int sm[256];
    int tid = threadIdx.x;
    int v = (tid < NB_SCAN) ? g_bsum[tid] : 0;
    sm[tid] = v;
    __syncthreads();
#pragma unroll
    for (int o = 1; o < 256; o <<= 1) {
        int u = (tid >= o) ? sm[tid - o] : 0;
        __syncthreads();
        sm[tid] += u;
        __syncthreads();
    }
    if (tid < NB_SCAN) g_boff[tid] = sm[tid] - v;   // exclusive
    if (tid == 255) g_off[N_NODES] = sm[255];
}

// scan phase 3: local exclusive scan + block offset; re-zero g_cnt for next run
__global__ __launch_bounds__(SCAN_B)
void scan3_kernel() {
    __shared__ int ws[SCAN_B / 32];
    int idx  = blockIdx.x * SCAN_B + threadIdx.x;
    int lane = threadIdx.x & 31;
    int wid  = threadIdx.x >> 5;
    int v = 0;
    if (idx < N_NODES) { v = g_cnt[idx]; g_cnt[idx] = 0; }
    // inclusive warp scan
    int s = v;
#pragma unroll
    for (int o = 1; o < 32; o <<= 1) {
        int u = __shfl_up_sync(0xffffffffu, s, o);
        if (lane >= o) s += u;
    }
    if (lane == 31) ws[wid] = s;
    __syncthreads();
    if (wid == 0) {                          // WHOLE warp 0 executes the shfls
        int t = (lane < SCAN_B / 32) ? ws[lane] : 0;
#pragma unroll
        for (int o = 1; o < SCAN_B / 32; o <<= 1) {
            int u = __shfl_up_sync(0xffffffffu, t, o, SCAN_B / 32);
            if (lane >= o) t += u;
        }
        if (lane < SCAN_B / 32) ws[lane] = t;
    }
    __syncthreads();
    int base = g_boff[blockIdx.x] + (wid ? ws[wid - 1] : 0);
    if (idx < N_NODES) g_off[idx] = base + s - v;   // exclusive
}

// scatter bumps g_off[t] directly: post-scatter g_off[i] == end of node i
__global__ void scatter_kernel(const int* __restrict__ ei) {
    int e = blockIdx.x * blockDim.x + threadIdx.x;
    if (e < N_EDGES) {
        int s = ei[e];
        int t = ei[N_EDGES + e];
        int pos = atomicAdd(&g_off[t], 1);
        g_esrc[pos] = s;
    }
}

// ---------------- warp-per-node online-softmax aggregation -------------------
// beg = i ? g_off[i-1] : 0, end = g_off[i]  (offsets are post-scatter-shifted)
__global__ __launch_bounds__(256)
void agg_kernel(const float* __restrict__ att,
                const float* __restrict__ bias,
                float* __restrict__ out) {
    int w    = (blockIdx.x * blockDim.x + threadIdx.x) >> 5;
    int lane = threadIdx.x & 31;
    if (w >= N_NODES) return;
    const int i  = w;
    const int c0 = lane << 2;

    const float4 xlv = *(const float4*)(g_xl + i * CH + c0);
    const float4 av  = *(const float4*)(att + c0);
    const float4 xrs = *(const float4*)(g_xr + i * CH + c0);

    // self-loop logit
    float s0 = xlv.x + xrs.x; s0 = s0 > 0.f ? s0 : NEG_SLOPE * s0;
    float s1 = xlv.y + xrs.y; s1 = s1 > 0.f ? s1 : NEG_SLOPE * s1;
    float s2 = xlv.z + xrs.z; s2 = s2 > 0.f ? s2 : NEG_SLOPE * s2;
    float s3 = xlv.w + xrs.w; s3 = s3 > 0.f ? s3 : NEG_SLOPE * s3;
    float p = av.x * s0 + av.y * s1 + av.z * s2 + av.w * s3;
#pragma unroll
    for (int o = 1; o < 8; o <<= 1) p += __shfl_xor_sync(0xffffffffu, p, o);

    float m = p;
    float d = 1.0f;
    float4 acc = xrs;

    const int beg = i ? __ldg(&g_off[i - 1]) : 0;
    const int end = __ldg(&g_off[i]);

    // software pipeline: prefetch next gather while reducing current (MLP=2)
    float4 xv_next = make_float4(0.f, 0.f, 0.f, 0.f);
    if (beg < end) {
        int src0 = __ldg(&g_esrc[beg]);
        xv_next = *(const float4*)(g_xr + src0 * CH + c0);
    }
    for (int e = beg; e < end; e++) {
        float4 xv = xv_next;
        if (e + 1 < end) {
            int sn = __ldg(&g_esrc[e + 1]);
            xv_next = *(const float4*)(g_xr + sn * CH + c0);
        }
        float t0 = xlv.x + xv.x; t0 = t0 > 0.f ? t0 : NEG_SLOPE * t0;
        float t1 = xlv.y + xv.y; t1 = t1 > 0.f ? t1 : NEG_SLOPE * t1;
        float t2 = xlv.z + xv.z; t2 = t2 > 0.f ? t2 : NEG_SLOPE * t2;
        float t3 = xlv.w + xv.w; t3 = t3 > 0.f ? t3 : NEG_SLOPE * t3;
        float q = av.x * t0 + av.y * t1 + av.z * t2 + av.w * t3;
#pragma unroll
        for (int o = 1; o < 8; o <<= 1) q += __shfl_xor_sync(0xffffffffu, q, o);

        float nm = fmaxf(m, q);
        float wm = __expf(m - nm);
        float wq = __expf(q - nm);
        d = d * wm + wq;
        acc.x = acc.x * wm + wq * xv.x;
        acc.y = acc.y * wm + wq * xv.y;
        acc.z = acc.z * wm + wq * xv.z;
        acc.w = acc.w * wm + wq * xv.w;
        m = nm;
    }

    float inv = 1.0f / d;
    const float4 bv = *(const float4*)(bias + c0);
    float4 r = make_float4(acc.x * inv + bv.x, acc.y * inv + bv.y,
                           acc.z * inv + bv.z, acc.w * inv + bv.w);
    *(float4*)(out + i * CH + c0) = r;
}

// ---------------- launch ------------------------------------------------------
extern "C" void kernel_launch(void* const* d_in, const int* in_sizes, int n_in,
                              void* d_out, int out_size) {
    const float* x    = (const float*)d_in[0];
    const int*   ei   = (const int*)d_in[1];     // int32 (JAX x64 disabled)
    const float* Wl   = (const float*)d_in[2];
    const float* bl   = (const float*)d_in[3];
    const float* Wr   = (const float*)d_in[4];
    const float* br   = (const float*)d_in[5];
    const float* att  = (const float*)d_in[6];
    const float* bias = (const float*)d_in[7];
    float*       out  = (float*)d_out;

    dim3 gg((N_NODES + BM - 1) / BM, 2);
    gemm_kernel<<<gg, 256>>>(x, Wl, bl, Wr, br);

    count_kernel<<<(N_EDGES + 255) / 256, 256>>>(ei);
    scan1_kernel<<<NB_SCAN, SCAN_B>>>();
    scan2_kernel<<<1, 256>>>();
    scan3_kernel<<<NB_SCAN, SCAN_B>>>();
    scatter_kernel<<<(N_EDGES + 255) / 256, 256>>>(ei);

    agg_kernel<<<(N_NODES * 32 + 255) / 256, 256>>>(att, bias, out);
}

// round 6
// speedup vs baseline: 1.4328x; 1.1851x over previous
#include <cuda_runtime.h>

#define N_NODES 50000
#define N_EDGES 800000
#define CH 128          // HEADS*OUT_CH = 4*32
#define NEG_SLOPE 0.2f
#define SCAN_B 256
#define NB_SCAN ((N_NODES + SCAN_B - 1) / SCAN_B)   // 196

// ---------------- scratch (static device memory; zero-init at load) ----------
__device__ __align__(16) float g_xl[N_NODES * CH];   // target projection
__device__ __align__(16) float g_xr[N_NODES * CH];   // source projection
__device__ int g_cnt[N_NODES];        // zero-initialized; re-zeroed by scan3
__device__ int g_off[N_NODES + 1];
__device__ int g_esrc[N_EDGES];
__device__ int g_bsum[NB_SCAN];
__device__ int g_boff[NB_SCAN];

// ---------------- packed f32x2 helpers (FFMA2 — 2x fp32 rate on sm_103a) -----
__device__ __forceinline__ void fma2(unsigned long long& d,
                                     unsigned long long a,
                                     unsigned long long b) {
    asm("fma.rn.f32x2 %0, %1, %2, %0;" : "+l"(d) : "l"(a), "l"(b));
}
__device__ __forceinline__ unsigned long long dup2(float x) {
    unsigned long long r;
    asm("mov.b64 %0, {%1, %1};" : "=l"(r) : "f"(x));
    return r;
}
__device__ __forceinline__ float2 unpack2(unsigned long long v) {
    float2 r;
    asm("mov.b64 {%0, %1}, %2;" : "=f"(r.x), "=f"(r.y) : "l"(v));
    return r;
}

// ---------------- fused dual projection GEMM --------------------------------
// 128 nodes x 128 outs per block, K in 8 tiles of 16. Per thread: 4 node-PAIRS
// (packed f32x2) x 8 outs. X staged transposed XsT[k][n] (pairs -> LDS.64,
// lane-consecutive, conflict-free). W staged duplicated Wdup[k][o]={w,w}
// (LDS.64 gives the packed operand directly, no MOVs, conflict-free).
#define BM 128
#define KT 16
#define XTLD 132          // floats per XsT row (pad)
#define WDLD 130          // float2 per Wdup row (pad)

__global__ __launch_bounds__(256, 2)
void gemm_kernel(const float* __restrict__ X,
                 const float* __restrict__ Wl, const float* __restrict__ bl,
                 const float* __restrict__ Wr, const float* __restrict__ br) {
    __shared__ __align__(16) float XsT[KT * XTLD];
    __shared__ unsigned long long Wdup[KT * WDLD];

    const float* W    = blockIdx.y ? Wr : Wl;
    const float* bias = blockIdx.y ? br : bl;
    float* dst        = blockIdx.y ? g_xr : g_xl;

    const int tid = threadIdx.x;
    const int nb  = blockIdx.x * BM;
    const int og  = tid & 15;      // out group: outs og + 16*j
    const int ng  = tid >> 4;      // node group: pairs at ng*2 + 32*i

    unsigned long long acc[4][8];
#pragma unroll
    for (int i = 0; i < 4; i++)
#pragma unroll
        for (int j = 0; j < 8; j++) acc[i][j] = 0ull;

    for (int kt = 0; kt < CH; kt += KT) {
        // stage X transposed: 128 nodes x 16 k = 512 float4, 2 per thread
#pragma unroll
        for (int t = 0; t < 2; t++) {
            int idx = tid + t * 256;           // 0..511
            int n   = idx >> 2;
            int q4  = (idx & 3) << 2;
            int gn  = nb + n;
            float4 v = make_float4(0.f, 0.f, 0.f, 0.f);
            if (gn < N_NODES) v = *(const float4*)(X + gn * CH + kt + q4);
            XsT[(q4 + 0) * XTLD + n] = v.x;
            XsT[(q4 + 1) * XTLD + n] = v.y;
            XsT[(q4 + 2) * XTLD + n] = v.z;
            XsT[(q4 + 3) * XTLD + n] = v.w;
        }
        // stage W duplicated: 128 outs x 16 k = 512 float4, 2 per thread
#pragma unroll
        for (int t = 0; t < 2; t++) {
            int idx = tid + t * 256;
            int o   = idx >> 2;
            int q4  = (idx & 3) << 2;
            float4 w = *(const float4*)(W + o * CH + kt + q4);
            Wdup[(q4 + 0) * WDLD + o] = dup2(w.x);
            Wdup[(q4 + 1) * WDLD + o] = dup2(w.y);
            Wdup[(q4 + 2) * WDLD + o] = dup2(w.z);
            Wdup[(q4 + 3) * WDLD + o] = dup2(w.w);
        }
        __syncthreads();

#pragma unroll
        for (int k = 0; k < KT; k++) {
            const unsigned long long* xr =
                (const unsigned long long*)(XsT + k * XTLD);
            const unsigned long long* wr = Wdup + k * WDLD;
            unsigned long long xp0 = xr[ng];
            unsigned long long xp1 = xr[ng + 16];
            unsigned long long xp2 = xr[ng + 32];
            unsigned long long xp3 = xr[ng + 48];
#pragma unroll
            for (int j = 0; j < 8; j++) {
                unsigned long long wp = wr[og + 16 * j];
                fma2(acc[0][j], xp0, wp);
                fma2(acc[1][j], xp1, wp);
                fma2(acc[2][j], xp2, wp);
                fma2(acc[3][j], xp3, wp);
            }
        }
        __syncthreads();
    }

    float bv[8];
#pragma unroll
    for (int j = 0; j < 8; j++) bv[j] = __ldg(&bias[og + 16 * j]);

#pragma unroll
    for (int i = 0; i < 4; i++) {
        int n0 = nb + ng * 2 + 32 * i;
        bool v0 = n0 < N_NODES;
        bool v1 = n0 + 1 < N_NODES;
#pragma unroll
        for (int j = 0; j < 8; j++) {
            float2 p = unpack2(acc[i][j]);
            int o = og + 16 * j;
            if (v0) dst[n0 * CH + o]       = p.x + bv[j];
            if (v1) dst[(n0 + 1) * CH + o] = p.y + bv[j];
        }
    }
}

// ---------------- CSR build --------------------------------------------------
// edge_index is int32, layout [2][N_EDGES]: row0 = src, row1 = tgt.
__global__ void count_kernel(const int* __restrict__ ei) {
    int e = blockIdx.x * blockDim.x + threadIdx.x;
    if (e < N_EDGES) atomicAdd(&g_cnt[ei[N_EDGES + e]], 1);
}

// scan phase 1: per-block sums of g_cnt
__global__ __launch_bounds__(SCAN_B)
void scan1_kernel() {
    __shared__ int ws[SCAN_B / 32];
    int idx  = blockIdx.x * SCAN_B + threadIdx.x;
    int v    = (idx < N_NODES) ? g_cnt[idx] : 0;
#pragma unroll
    for (int o = 16; o > 0; o >>= 1) v += __shfl_xor_sync(0xffffffffu, v, o);
    if ((threadIdx.x & 31) == 0) ws[threadIdx.x >> 5] = v;
    __syncthreads();
    if (threadIdx.x < 32) {
        int s = (threadIdx.x < SCAN_B / 32) ? ws[threadIdx.x] : 0;
#pragma unroll
        for (int o = SCAN_B / 64; o > 0; o >>= 1)
            s += __shfl_xor_sync(0xffffffffu, s, o, SCAN_B / 32);
        if (threadIdx.x == 0) g_bsum[blockIdx.x] = s;
    }
}

// scan phase 2: exclusive scan of NB_SCAN block sums (warp shuffles, 2 barriers)
__global__ __launch_bounds__(256)
void scan2_kernel() {
    __shared__ int ws[8];
    int tid  = threadIdx.x;
    int lane = tid & 31;
    int wid  = tid >> 5;
    int v = (tid < NB_SCAN) ? g_bsum[tid] : 0;
    int s = v;
#pragma unroll
    for (int o = 1; o < 32; o <<= 1) {
        int u = __shfl_up_sync(0xffffffffu, s, o);
        if (lane >= o) s += u;
    }
    if (lane == 31) ws[wid] = s;
    __syncthreads();
    if (wid == 0) {
        int t = (lane < 8) ? ws[lane] : 0;
#pragma unroll
        for (int o = 1; o < 8; o <<= 1) {
            int u = __shfl_up_sync(0xffffffffu, t, o, 8);
            if ((lane & 7) >= o) t += u;
        }
        if (lane < 8) ws[lane] = t;
    }
    __syncthreads();
    int incl = (wid ? ws[wid - 1] : 0) + s;
    if (tid < NB_SCAN) g_boff[tid] = incl - v;          // exclusive
    if (tid == NB_SCAN - 1) g_off[N_NODES] = incl;
}

// scan phase 3: local exclusive scan + block offset; re-zero g_cnt for next run
__global__ __launch_bounds__(SCAN_B)
void scan3_kernel() {
    __shared__ int ws[SCAN_B / 32];
    int idx  = blockIdx.x * SCAN_B + threadIdx.x;
    int lane = threadIdx.x & 31;
    int wid  = threadIdx.x >> 5;
    int v = 0;
    if (idx < N_NODES) { v = g_cnt[idx]; g_cnt[idx] = 0; }
    int s = v;
#pragma unroll
    for (int o = 1; o < 32; o <<= 1) {
        int u = __shfl_up_sync(0xffffffffu, s, o);
        if (lane >= o) s += u;
    }
    if (lane == 31) ws[wid] = s;
    __syncthreads();
    if (wid == 0) {
        int t = (lane < SCAN_B / 32) ? ws[lane] : 0;
#pragma unroll
        for (int o = 1; o < SCAN_B / 32; o <<= 1) {
            int u = __shfl_up_sync(0xffffffffu, t, o, SCAN_B / 32);
            if (lane >= o) t += u;
        }
        if (lane < SCAN_B / 32) ws[lane] = t;
    }
    __syncthreads();
    int base = g_boff[blockIdx.x] + (wid ? ws[wid - 1] : 0);
    if (idx < N_NODES) g_off[idx] = base + s - v;   // exclusive
}

// scatter bumps g_off[t] directly: post-scatter g_off[i] == end of node i
__global__ void scatter_kernel(const int* __restrict__ ei) {
    int e = blockIdx.x * blockDim.x + threadIdx.x;
    if (e < N_EDGES) {
        int s = ei[e];
        int t = ei[N_EDGES + e];
        int pos = atomicAdd(&g_off[t], 1);
        g_esrc[pos] = s;
    }
}

// ---------------- warp-per-node online-softmax aggregation -------------------
// beg = i ? g_off[i-1] : 0, end = g_off[i]  (offsets are post-scatter-shifted)
__global__ __launch_bounds__(256)
void agg_kernel(const float* __restrict__ att,
                const float* __restrict__ bias,
                float* __restrict__ out) {
    int w    = (blockIdx.x * blockDim.x + threadIdx.x) >> 5;
    int lane = threadIdx.x & 31;
    if (w >= N_NODES) return;
    const int i  = w;
    const int c0 = lane << 2;

    const float4 xlv = *(const float4*)(g_xl + i * CH + c0);
    const float4 av  = *(const float4*)(att + c0);
    const float4 xrs = *(const float4*)(g_xr + i * CH + c0);

    // self-loop logit
    float s0 = xlv.x + xrs.x; s0 = s0 > 0.f ? s0 : NEG_SLOPE * s0;
    float s1 = xlv.y + xrs.y; s1 = s1 > 0.f ? s1 : NEG_SLOPE * s1;
    float s2 = xlv.z + xrs.z; s2 = s2 > 0.f ? s2 : NEG_SLOPE * s2;
    float s3 = xlv.w + xrs.w; s3 = s3 > 0.f ? s3 : NEG_SLOPE * s3;
    float p = av.x * s0 + av.y * s1 + av.z * s2 + av.w * s3;
#pragma unroll
    for (int o = 1; o < 8; o <<= 1) p += __shfl_xor_sync(0xffffffffu, p, o);

    float m = p;
    float d = 1.0f;
    float4 acc = xrs;

    const int beg = i ? __ldg(&g_off[i - 1]) : 0;
    const int end = __ldg(&g_off[i]);

    // software pipeline: prefetch next gather while reducing current (MLP=2)
    float4 xv_next = make_float4(0.f, 0.f, 0.f, 0.f);
    if (beg < end) {
        int src0 = __ldg(&g_esrc[beg]);
        xv_next = *(const float4*)(g_xr + src0 * CH + c0);
    }
    for (int e = beg; e < end; e++) {
        float4 xv = xv_next;
        if (e + 1 < end) {
            int sn = __ldg(&g_esrc[e + 1]);
            xv_next = *(const float4*)(g_xr + sn * CH + c0);
        }
        float t0 = xlv.x + xv.x; t0 = t0 > 0.f ? t0 : NEG_SLOPE * t0;
        float t1 = xlv.y + xv.y; t1 = t1 > 0.f ? t1 : NEG_SLOPE * t1;
        float t2 = xlv.z + xv.z; t2 = t2 > 0.f ? t2 : NEG_SLOPE * t2;
        float t3 = xlv.w + xv.w; t3 = t3 > 0.f ? t3 : NEG_SLOPE * t3;
        float q = av.x * t0 + av.y * t1 + av.z * t2 + av.w * t3;
#pragma unroll
        for (int o = 1; o < 8; o <<= 1) q += __shfl_xor_sync(0xffffffffu, q, o);

        float nm = fmaxf(m, q);
        float wm = __expf(m - nm);
        float wq = __expf(q - nm);
        d = d * wm + wq;
        acc.x = acc.x * wm + wq * xv.x;
        acc.y = acc.y * wm + wq * xv.y;
        acc.z = acc.z * wm + wq * xv.z;
        acc.w = acc.w * wm + wq * xv.w;
        m = nm;
    }

    float inv = 1.0f / d;
    const float4 bv = *(const float4*)(bias + c0);
    float4 r = make_float4(acc.x * inv + bv.x, acc.y * inv + bv.y,
                           acc.z * inv + bv.z, acc.w * inv + bv.w);
    *(float4*)(out + i * CH + c0) = r;
}

// ---------------- launch ------------------------------------------------------
extern "C" void kernel_launch(void* const* d_in, const int* in_sizes, int n_in,
                              void* d_out, int out_size) {
    const float* x    = (const float*)d_in[0];
    const int*   ei   = (const int*)d_in[1];     // int32 (JAX x64 disabled)
    const float* Wl   = (const float*)d_in[2];
    const float* bl   = (const float*)d_in[3];
    const float* Wr   = (const float*)d_in[4];
    const float* br   = (const float*)d_in[5];
    const float* att  = (const float*)d_in[6];
    const float* bias = (const float*)d_in[7];
    float*       out  = (float*)d_out;

    dim3 gg((N_NODES + BM - 1) / BM, 2);
    gemm_kernel<<<gg, 256>>>(x, Wl, bl, Wr, br);

    count_kernel<<<(N_EDGES + 255) / 256, 256>>>(ei);
    scan1_kernel<<<NB_SCAN, SCAN_B>>>();
    scan2_kernel<<<1, 256>>>();
    scan3_kernel<<<NB_SCAN, SCAN_B>>>();
    scatter_kernel<<<(N_EDGES + 255) / 256, 256>>>(ei);

    agg_kernel<<<(N_NODES * 32 + 255) / 256, 256>>>(att, bias, out);
}

// round 7
// speedup vs baseline: 1.4865x; 1.0375x over previous
#include <cuda_runtime.h>

#define N_NODES 50000
#define N_EDGES 800000
#define CH 128          // HEADS*OUT_CH = 4*32
#define NEG_SLOPE 0.2f
#define SCAN_B 256
#define NB_SCAN ((N_NODES + SCAN_B - 1) / SCAN_B)   // 196
#define NB_CSR 784                                   // blocks in csr kernel
#define NBG_M ((N_NODES + 127) / 128)                // 391 gemm blocks per mat
#define NBG (2 * NBG_M)                              // 782
#define NB_CNT ((N_EDGES + 255) / 256)               // 3125 count blocks

// ---------------- scratch (static device memory; zero-init at load) ----------
__device__ __align__(16) float g_xl[N_NODES * CH];   // target projection
__device__ __align__(16) float g_xr[N_NODES * CH];   // source projection
__device__ int g_cnt[N_NODES];        // zero-init; consumed+re-zeroed by csr
__device__ int g_off[N_NODES + 1];
__device__ int g_esrc[N_EDGES];
__device__ int g_bsum[NB_SCAN];
__device__ int g_sync1, g_sync2, g_sync3;   // self-resetting spin counters

// ---------------- packed f32x2 helpers (FFMA2 — 2x fp32 rate on sm_103a) -----
__device__ __forceinline__ void fma2(unsigned long long& d,
                                     unsigned long long a,
                                     unsigned long long b) {
    asm("fma.rn.f32x2 %0, %1, %2, %0;" : "+l"(d) : "l"(a), "l"(b));
}
__device__ __forceinline__ unsigned long long dup2(float x) {
    unsigned long long r;
    asm("mov.b64 %0, {%1, %1};" : "=l"(r) : "f"(x));
    return r;
}
__device__ __forceinline__ float2 unpack2(unsigned long long v) {
    float2 r;
    asm("mov.b64 {%0, %1}, %2;" : "=f"(r.x), "=f"(r.y) : "l"(v));
    return r;
}

// ---------------- K1: fused dual projection GEMM + edge count ----------------
// Blocks [0, NBG): GEMM, 128 nodes x 128 outs, K in 8 tiles of 16.
// Blocks [NBG, NBG+NB_CNT): histogram of edge targets into g_cnt.
#define BM 128
#define KT 16
#define XTLD 132
#define WDLD 130

__global__ __launch_bounds__(256, 2)
void gemm_count_kernel(const float* __restrict__ X,
                       const float* __restrict__ Wl, const float* __restrict__ bl,
                       const float* __restrict__ Wr, const float* __restrict__ br,
                       const int* __restrict__ ei) {
    __shared__ __align__(16) float XsT[KT * XTLD];
    __shared__ unsigned long long Wdup[KT * WDLD];

    if (blockIdx.x >= NBG) {               // ---- count path ----
        int e = (blockIdx.x - NBG) * 256 + threadIdx.x;
        if (e < N_EDGES) atomicAdd(&g_cnt[ei[N_EDGES + e]], 1);
        return;
    }

    const int by = (blockIdx.x >= NBG_M) ? 1 : 0;
    const int bx = blockIdx.x - (by ? NBG_M : 0);

    const float* W    = by ? Wr : Wl;
    const float* bias = by ? br : bl;
    float* dst        = by ? g_xr : g_xl;

    const int tid = threadIdx.x;
    const int nb  = bx * BM;
    const int og  = tid & 15;      // outs og + 16*j
    const int ng  = tid >> 4;      // node pairs at ng*2 + 32*i

    unsigned long long acc[4][8];
#pragma unroll
    for (int i = 0; i < 4; i++)
#pragma unroll
        for (int j = 0; j < 8; j++) acc[i][j] = 0ull;

    for (int kt = 0; kt < CH; kt += KT) {
#pragma unroll
        for (int t = 0; t < 2; t++) {
            int idx = tid + t * 256;
            int n   = idx >> 2;
            int q4  = (idx & 3) << 2;
            int gn  = nb + n;
            float4 v = make_float4(0.f, 0.f, 0.f, 0.f);
            if (gn < N_NODES) v = *(const float4*)(X + gn * CH + kt + q4);
            XsT[(q4 + 0) * XTLD + n] = v.x;
            XsT[(q4 + 1) * XTLD + n] = v.y;
            XsT[(q4 + 2) * XTLD + n] = v.z;
            XsT[(q4 + 3) * XTLD + n] = v.w;
        }
#pragma unroll
        for (int t = 0; t < 2; t++) {
            int idx = tid + t * 256;
            int o   = idx >> 2;
            int q4  = (idx & 3) << 2;
            float4 w = *(const float4*)(W + o * CH + kt + q4);
            Wdup[(q4 + 0) * WDLD + o] = dup2(w.x);
            Wdup[(q4 + 1) * WDLD + o] = dup2(w.y);
            Wdup[(q4 + 2) * WDLD + o] = dup2(w.z);
            Wdup[(q4 + 3) * WDLD + o] = dup2(w.w);
        }
        __syncthreads();

#pragma unroll
        for (int k = 0; k < KT; k++) {
            const unsigned long long* xr =
                (const unsigned long long*)(XsT + k * XTLD);
            const unsigned long long* wr = Wdup + k * WDLD;
            unsigned long long xp0 = xr[ng];
            unsigned long long xp1 = xr[ng + 16];
            unsigned long long xp2 = xr[ng + 32];
            unsigned long long xp3 = xr[ng + 48];
#pragma unroll
            for (int j = 0; j < 8; j++) {
                unsigned long long wp = wr[og + 16 * j];
                fma2(acc[0][j], xp0, wp);
                fma2(acc[1][j], xp1, wp);
                fma2(acc[2][j], xp2, wp);
                fma2(acc[3][j], xp3, wp);
            }
        }
        __syncthreads();
    }

    float bv[8];
#pragma unroll
    for (int j = 0; j < 8; j++) bv[j] = __ldg(&bias[og + 16 * j]);

#pragma unroll
    for (int i = 0; i < 4; i++) {
        int n0 = nb + ng * 2 + 32 * i;
        bool v0 = n0 < N_NODES;
        bool v1 = n0 + 1 < N_NODES;
#pragma unroll
        for (int j = 0; j < 8; j++) {
            float2 p = unpack2(acc[i][j]);
            int o = og + 16 * j;
            if (v0) dst[n0 * CH + o]       = p.x + bv[j];
            if (v1) dst[(n0 + 1) * CH + o] = p.y + bv[j];
        }
    }
}

// ---------------- K2: fused scan (2-level) + scatter, spin-wait grid sync ----
// Blocks 0..NB_SCAN-1 do the scan; ALL NB_CSR blocks join for the scatter.
// All NB_CSR blocks are co-resident (tiny smem/regs), so spins cannot deadlock.
__global__ __launch_bounds__(SCAN_B)
void csr_kernel(const int* __restrict__ ei) {
    __shared__ int ws[8];
    __shared__ int s_base;
    const int b    = blockIdx.x;
    const int tid  = threadIdx.x;
    const int lane = tid & 31;
    const int wid  = tid >> 5;

    if (b < NB_SCAN) {
        int idx = b * SCAN_B + tid;
        int v = 0;
        if (idx < N_NODES) { v = g_cnt[idx]; g_cnt[idx] = 0; }
        // block-local inclusive scan
        int s = v;
#pragma unroll
        for (int o = 1; o < 32; o <<= 1) {
            int u = __shfl_up_sync(0xffffffffu, s, o);
            if (lane >= o) s += u;
        }
        if (lane == 31) ws[wid] = s;
        __syncthreads();
        if (wid == 0) {
            int t = (lane < 8) ? ws[lane] : 0;
#pragma unroll
            for (int o = 1; o < 8; o <<= 1) {
                int u = __shfl_up_sync(0xffffffffu, t, o, 8);
                if ((lane & 7) >= o) t += u;
            }
            if (lane < 8) ws[lane] = t;
        }
        __syncthreads();
        int blocksum   = ws[7];
        int local_excl = (wid ? ws[wid - 1] : 0) + s - v;
        __syncthreads();                     // ws reused below

        if (tid == 0) {
            g_bsum[b] = blocksum;
            __threadfence();
            atomicAdd(&g_sync1, 1);
            while (*(volatile int*)&g_sync1 < NB_SCAN) {}
            __threadfence();
        }
        __syncthreads();

        // prefix over preceding block sums (NB_SCAN=196 < 256 threads)
        int pv = (tid < b) ? g_bsum[tid] : 0;
#pragma unroll
        for (int o = 16; o > 0; o >>= 1) pv += __shfl_xor_sync(0xffffffffu, pv, o);
        if (lane == 0) ws[wid] = pv;
        __syncthreads();
        if (tid == 0) {
            int tot = 0;
#pragma unroll
            for (int i = 0; i < 8; i++) tot += ws[i];
            s_base = tot;
        }
        __syncthreads();
        int base = s_base;

        if (idx < N_NODES) g_off[idx] = base + local_excl;    // exclusive
        if (b == NB_SCAN - 1 && tid == 0) g_off[N_NODES] = base + blocksum;

        if (tid == 0) {
            __threadfence();
            atomicAdd(&g_sync2, 1);
        }
    }

    // all blocks wait until offsets are complete, then reset counters
    if (tid == 0) {
        while (*(volatile int*)&g_sync2 < NB_SCAN) {}
        __threadfence();
        int t3 = atomicAdd(&g_sync3, 1);
        if (t3 == NB_CSR - 1) { g_sync1 = 0; g_sync2 = 0; g_sync3 = 0; }
    }
    __syncthreads();

    // scatter: bump g_off[t] directly (post-scatter g_off[i] == end of node i)
    for (int e = b * SCAN_B + tid; e < N_EDGES; e += NB_CSR * SCAN_B) {
        int sp = ei[e];
        int tg = ei[N_EDGES + e];
        int pos = atomicAdd(&g_off[tg], 1);
        g_esrc[pos] = sp;
    }
}

// ---------------- K3: warp-per-node online-softmax aggregation ---------------
// beg = i ? g_off[i-1] : 0, end = g_off[i]  (offsets are post-scatter-shifted)
__global__ __launch_bounds__(256)
void agg_kernel(const float* __restrict__ att,
                const float* __restrict__ bias,
                float* __restrict__ out) {
    int w    = (blockIdx.x * blockDim.x + threadIdx.x) >> 5;
    int lane = threadIdx.x & 31;
    if (w >= N_NODES) return;
    const int i  = w;
    const int c0 = lane << 2;

    const float4 xlv = *(const float4*)(g_xl + i * CH + c0);
    const float4 av  = *(const float4*)(att + c0);
    const float4 xrs = *(const float4*)(g_xr + i * CH + c0);

    // self-loop logit
    float s0 = xlv.x + xrs.x; s0 = s0 > 0.f ? s0 : NEG_SLOPE * s0;
    float s1 = xlv.y + xrs.y; s1 = s1 > 0.f ? s1 : NEG_SLOPE * s1;
    float s2 = xlv.z + xrs.z; s2 = s2 > 0.f ? s2 : NEG_SLOPE * s2;
    float s3 = xlv.w + xrs.w; s3 = s3 > 0.f ? s3 : NEG_SLOPE * s3;
    float p = av.x * s0 + av.y * s1 + av.z * s2 + av.w * s3;
#pragma unroll
    for (int o = 1; o < 8; o <<= 1) p += __shfl_xor_sync(0xffffffffu, p, o);

    float m = p;
    float d = 1.0f;
    float4 acc = xrs;

    const int beg = i ? __ldg(&g_off[i - 1]) : 0;
    const int end = __ldg(&g_off[i]);

    // software pipeline: prefetch next gather while reducing current (MLP=2)
    float4 xv_next = make_float4(0.f, 0.f, 0.f, 0.f);
    if (beg < end) {
        int src0 = __ldg(&g_esrc[beg]);
        xv_next = *(const float4*)(g_xr + src0 * CH + c0);
    }
    for (int e = beg; e < end; e++) {
        float4 xv = xv_next;
        if (e + 1 < end) {
            int sn = __ldg(&g_esrc[e + 1]);
            xv_next = *(const float4*)(g_xr + sn * CH + c0);
        }
        float t0 = xlv.x + xv.x; t0 = t0 > 0.f ? t0 : NEG_SLOPE * t0;
        float t1 = xlv.y + xv.y; t1 = t1 > 0.f ? t1 : NEG_SLOPE * t1;
        float t2 = xlv.z + xv.z; t2 = t2 > 0.f ? t2 : NEG_SLOPE * t2;
        float t3 = xlv.w + xv.w; t3 = t3 > 0.f ? t3 : NEG_SLOPE * t3;
        float q = av.x * t0 + av.y * t1 + av.z * t2 + av.w * t3;
#pragma unroll
        for (int o = 1; o < 8; o <<= 1) q += __shfl_xor_sync(0xffffffffu, q, o);

        float nm = fmaxf(m, q);
        float wm = __expf(m - nm);
        float wq = __expf(q - nm);
        d = d * wm + wq;
        acc.x = acc.x * wm + wq * xv.x;
        acc.y = acc.y * wm + wq * xv.y;
        acc.z = acc.z * wm + wq * xv.z;
        acc.w = acc.w * wm + wq * xv.w;
        m = nm;
    }

    float inv = 1.0f / d;
    const float4 bv = *(const float4*)(bias + c0);
    float4 r = make_float4(acc.x * inv + bv.x, acc.y * inv + bv.y,
                           acc.z * inv + bv.z, acc.w * inv + bv.w);
    *(float4*)(out + i * CH + c0) = r;
}

// ---------------- launch ------------------------------------------------------
extern "C" void kernel_launch(void* const* d_in, const int* in_sizes, int n_in,
                              void* d_out, int out_size) {
    const float* x    = (const float*)d_in[0];
    const int*   ei   = (const int*)d_in[1];     // int32 (JAX x64 disabled)
    const float* Wl   = (const float*)d_in[2];
    const float* bl   = (const float*)d_in[3];
    const float* Wr   = (const float*)d_in[4];
    const float* br   = (const float*)d_in[5];
    const float* att  = (const float*)d_in[6];
    const float* bias = (const float*)d_in[7];
    float*       out  = (float*)d_out;

    gemm_count_kernel<<<NBG + NB_CNT, 256>>>(x, Wl, bl, Wr, br, ei);
    csr_kernel<<<NB_CSR, SCAN_B>>>(ei);
    agg_kernel<<<(N_NODES * 32 + 255) / 256, 256>>>(att, bias, out);
}

// round 8
// speedup vs baseline: 1.5532x; 1.0449x over previous
#include <cuda_runtime.h>

#define N_NODES 50000
#define N_EDGES 800000
#define CH 128          // HEADS*OUT_CH = 4*32
#define NEG_SLOPE 0.2f
#define SCAN_B 256
#define NB_SCAN ((N_NODES + SCAN_B - 1) / SCAN_B)   // 196
#define NB_CSR 784                                   // blocks in csr kernel
#define NBG_M ((N_NODES + 127) / 128)                // 391 gemm blocks per mat
#define NBG (2 * NBG_M)                              // 782
#define NB_CNT ((N_EDGES + 255) / 256)               // 3125 count blocks

// ---------------- scratch (static device memory; zero-init at load) ----------
__device__ __align__(16) float g_xl[N_NODES * CH];   // target projection
__device__ __align__(16) float g_xr[N_NODES * CH];   // source projection
__device__ int g_cnt[N_NODES];        // zero-init; consumed+re-zeroed by csr
__device__ int g_off[N_NODES + 1];
__device__ int g_esrc[N_EDGES];
__device__ int g_bsum[NB_SCAN];
__device__ int g_sync1, g_sync2, g_sync3;   // self-resetting spin counters

// ---------------- packed f32x2 helpers (FFMA2 — 2x fp32 rate on sm_103a) -----
__device__ __forceinline__ void fma2(unsigned long long& d,
                                     unsigned long long a,
                                     unsigned long long b) {
    asm("fma.rn.f32x2 %0, %1, %2, %0;" : "+l"(d) : "l"(a), "l"(b));
}
__device__ __forceinline__ unsigned long long dup2(float x) {
    unsigned long long r;
    asm("mov.b64 %0, {%1, %1};" : "=l"(r) : "f"(x));
    return r;
}
__device__ __forceinline__ float2 unpack2(unsigned long long v) {
    float2 r;
    asm("mov.b64 {%0, %1}, %2;" : "=f"(r.x), "=f"(r.y) : "l"(v));
    return r;
}

// ---------------- K1: fused dual projection GEMM + edge count ----------------
// Blocks [0, NBG): GEMM, 128 nodes x 128 outs, K in 8 tiles of 16.
// Per thread: 4 node-pairs (packed f32x2) x 8 outs.
// X in smem transposed XsT[k][n] -> LDS.64 of node pairs (2 wf each).
// W in smem PLAIN floats Wsp[k][o] -> LDS.32 (1 wf) + register dup2.
// Crossbar cost/warp-k: 4*2 + 8*1 = 16 wf == FFMA2 demand -> balanced.
// Blocks [NBG, NBG+NB_CNT): histogram of edge targets into g_cnt.
#define BM 128
#define KT 16
#define XTLD 132
#define WLD 132

__global__ __launch_bounds__(256, 2)
void gemm_count_kernel(const float* __restrict__ X,
                       const float* __restrict__ Wl, const float* __restrict__ bl,
                       const float* __restrict__ Wr, const float* __restrict__ br,
                       const int* __restrict__ ei) {
    __shared__ __align__(16) float XsT[KT * XTLD];
    __shared__ __align__(16) float Wsp[KT * WLD];

    if (blockIdx.x >= NBG) {               // ---- count path ----
        int e = (blockIdx.x - NBG) * 256 + threadIdx.x;
        if (e < N_EDGES) atomicAdd(&g_cnt[ei[N_EDGES + e]], 1);
        return;
    }

    const int by = (blockIdx.x >= NBG_M) ? 1 : 0;
    const int bx = blockIdx.x - (by ? NBG_M : 0);

    const float* W    = by ? Wr : Wl;
    const float* bias = by ? br : bl;
    float* dst        = by ? g_xr : g_xl;

    const int tid = threadIdx.x;
    const int nb  = bx * BM;
    const int og  = tid & 15;      // outs og + 16*j
    const int ng  = tid >> 4;      // node pairs at ng*2 + 32*i

    unsigned long long acc[4][8];
#pragma unroll
    for (int i = 0; i < 4; i++)
#pragma unroll
        for (int j = 0; j < 8; j++) acc[i][j] = 0ull;

    for (int kt = 0; kt < CH; kt += KT) {
        // stage X transposed: 128 nodes x 16 k = 512 float4, 2 per thread
#pragma unroll
        for (int t = 0; t < 2; t++) {
            int idx = tid + t * 256;
            int n   = idx >> 2;
            int q4  = (idx & 3) << 2;
            int gn  = nb + n;
            float4 v = make_float4(0.f, 0.f, 0.f, 0.f);
            if (gn < N_NODES) v = *(const float4*)(X + gn * CH + kt + q4);
            XsT[(q4 + 0) * XTLD + n] = v.x;
            XsT[(q4 + 1) * XTLD + n] = v.y;
            XsT[(q4 + 2) * XTLD + n] = v.z;
            XsT[(q4 + 3) * XTLD + n] = v.w;
        }
        // stage W transposed (plain): 128 outs x 16 k
#pragma unroll
        for (int t = 0; t < 2; t++) {
            int idx = tid + t * 256;
            int o   = idx >> 2;
            int q4  = (idx & 3) << 2;
            float4 w = *(const float4*)(W + o * CH + kt + q4);
            Wsp[(q4 + 0) * WLD + o] = w.x;
            Wsp[(q4 + 1) * WLD + o] = w.y;
            Wsp[(q4 + 2) * WLD + o] = w.z;
            Wsp[(q4 + 3) * WLD + o] = w.w;
        }
        __syncthreads();

#pragma unroll
        for (int k = 0; k < KT; k++) {
            const unsigned long long* xr =
                (const unsigned long long*)(XsT + k * XTLD);
            const float* wr = Wsp + k * WLD;
            unsigned long long xp0 = xr[ng];
            unsigned long long xp1 = xr[ng + 16];
            unsigned long long xp2 = xr[ng + 32];
            unsigned long long xp3 = xr[ng + 48];
#pragma unroll
            for (int j = 0; j < 8; j++) {
                unsigned long long wp = dup2(wr[og + 16 * j]);  // LDS.32 + MOV
                fma2(acc[0][j], xp0, wp);
                fma2(acc[1][j], xp1, wp);
                fma2(acc[2][j], xp2, wp);
                fma2(acc[3][j], xp3, wp);
            }
        }
        __syncthreads();
    }

    float bv[8];
#pragma unroll
    for (int j = 0; j < 8; j++) bv[j] = __ldg(&bias[og + 16 * j]);

#pragma unroll
    for (int i = 0; i < 4; i++) {
        int n0 = nb + ng * 2 + 32 * i;
        bool v0 = n0 < N_NODES;
        bool v1 = n0 + 1 < N_NODES;
#pragma unroll
        for (int j = 0; j < 8; j++) {
            float2 p = unpack2(acc[i][j]);
            int o = og + 16 * j;
            if (v0) dst[n0 * CH + o]       = p.x + bv[j];
            if (v1) dst[(n0 + 1) * CH + o] = p.y + bv[j];
        }
    }
}

// ---------------- K2: fused scan (2-level) + scatter, spin-wait grid sync ----
__global__ __launch_bounds__(SCAN_B)
void csr_kernel(const int* __restrict__ ei) {
    __shared__ int ws[8];
    __shared__ int s_base;
    const int b    = blockIdx.x;
    const int tid  = threadIdx.x;
    const int lane = tid & 31;
    const int wid  = tid >> 5;

    if (b < NB_SCAN) {
        int idx = b * SCAN_B + tid;
        int v = 0;
        if (idx < N_NODES) { v = g_cnt[idx]; g_cnt[idx] = 0; }
        int s = v;
#pragma unroll
        for (int o = 1; o < 32; o <<= 1) {
            int u = __shfl_up_sync(0xffffffffu, s, o);
            if (lane >= o) s += u;
        }
        if (lane == 31) ws[wid] = s;
        __syncthreads();
        if (wid == 0) {
            int t = (lane < 8) ? ws[lane] : 0;
#pragma unroll
            for (int o = 1; o < 8; o <<= 1) {
                int u = __shfl_up_sync(0xffffffffu, t, o, 8);
                if ((lane & 7) >= o) t += u;
            }
            if (lane < 8) ws[lane] = t;
        }
        __syncthreads();
        int blocksum   = ws[7];
        int local_excl = (wid ? ws[wid - 1] : 0) + s - v;
        __syncthreads();

        if (tid == 0) {
            g_bsum[b] = blocksum;
            __threadfence();
            atomicAdd(&g_sync1, 1);
            while (*(volatile int*)&g_sync1 < NB_SCAN) {}
            __threadfence();
        }
        __syncthreads();

        int pv = (tid < b) ? g_bsum[tid] : 0;
#pragma unroll
        for (int o = 16; o > 0; o >>= 1) pv += __shfl_xor_sync(0xffffffffu, pv, o);
        if (lane == 0) ws[wid] = pv;
        __syncthreads();
        if (tid == 0) {
            int tot = 0;
#pragma unroll
            for (int i = 0; i < 8; i++) tot += ws[i];
            s_base = tot;
        }
        __syncthreads();
        int base = s_base;

        if (idx < N_NODES) g_off[idx] = base + local_excl;
        if (b == NB_SCAN - 1 && tid == 0) g_off[N_NODES] = base + blocksum;

        if (tid == 0) {
            __threadfence();
            atomicAdd(&g_sync2, 1);
        }
    }

    if (tid == 0) {
        while (*(volatile int*)&g_sync2 < NB_SCAN) {}
        __threadfence();
        int t3 = atomicAdd(&g_sync3, 1);
        if (t3 == NB_CSR - 1) { g_sync1 = 0; g_sync2 = 0; g_sync3 = 0; }
    }
    __syncthreads();

    for (int e = b * SCAN_B + tid; e < N_EDGES; e += NB_CSR * SCAN_B) {
        int sp = ei[e];
        int tg = ei[N_EDGES + e];
        int pos = atomicAdd(&g_off[tg], 1);
        g_esrc[pos] = sp;
    }
}

// ---------------- K3: warp-per-node online-softmax aggregation ---------------
__global__ __launch_bounds__(256)
void agg_kernel(const float* __restrict__ att,
                const float* __restrict__ bias,
                float* __restrict__ out) {
    int w    = (blockIdx.x * blockDim.x + threadIdx.x) >> 5;
    int lane = threadIdx.x & 31;
    if (w >= N_NODES) return;
    const int i  = w;
    const int c0 = lane << 2;

    const float4 xlv = *(const float4*)(g_xl + i * CH + c0);
    const float4 av  = *(const float4*)(att + c0);
    const float4 xrs = *(const float4*)(g_xr + i * CH + c0);

    float s0 = xlv.x + xrs.x; s0 = s0 > 0.f ? s0 : NEG_SLOPE * s0;
    float s1 = xlv.y + xrs.y; s1 = s1 > 0.f ? s1 : NEG_SLOPE * s1;
    float s2 = xlv.z + xrs.z; s2 = s2 > 0.f ? s2 : NEG_SLOPE * s2;
    float s3 = xlv.w + xrs.w; s3 = s3 > 0.f ? s3 : NEG_SLOPE * s3;
    float p = av.x * s0 + av.y * s1 + av.z * s2 + av.w * s3;
#pragma unroll
    for (int o = 1; o < 8; o <<= 1) p += __shfl_xor_sync(0xffffffffu, p, o);

    float m = p;
    float d = 1.0f;
    float4 acc = xrs;

    const int beg = i ? __ldg(&g_off[i - 1]) : 0;
    const int end = __ldg(&g_off[i]);

    float4 xv_next = make_float4(0.f, 0.f, 0.f, 0.f);
    if (beg < end) {
        int src0 = __ldg(&g_esrc[beg]);
        xv_next = *(const float4*)(g_xr + src0 * CH + c0);
    }
    for (int e = beg; e < end; e++) {
        float4 xv = xv_next;
        if (e + 1 < end) {
            int sn = __ldg(&g_esrc[e + 1]);
            xv_next = *(const float4*)(g_xr + sn * CH + c0);
        }
        float t0 = xlv.x + xv.x; t0 = t0 > 0.f ? t0 : NEG_SLOPE * t0;
        float t1 = xlv.y + xv.y; t1 = t1 > 0.f ? t1 : NEG_SLOPE * t1;
        float t2 = xlv.z + xv.z; t2 = t2 > 0.f ? t2 : NEG_SLOPE * t2;
        float t3 = xlv.w + xv.w; t3 = t3 > 0.f ? t3 : NEG_SLOPE * t3;
        float q = av.x * t0 + av.y * t1 + av.z * t2 + av.w * t3;
#pragma unroll
        for (int o = 1; o < 8; o <<= 1) q += __shfl_xor_sync(0xffffffffu, q, o);

        float nm = fmaxf(m, q);
        float wm = __expf(m - nm);
        float wq = __expf(q - nm);
        d = d * wm + wq;
        acc.x = acc.x * wm + wq * xv.x;
        acc.y = acc.y * wm + wq * xv.y;
        acc.z = acc.z * wm + wq * xv.z;
        acc.w = acc.w * wm + wq * xv.w;
        m = nm;
    }

    float inv = 1.0f / d;
    const float4 bv = *(const float4*)(bias + c0);
    float4 r = make_float4(acc.x * inv + bv.x, acc.y * inv + bv.y,
                           acc.z * inv + bv.z, acc.w * inv + bv.w);
    *(float4*)(out + i * CH + c0) = r;
}

// ---------------- launch ------------------------------------------------------
extern "C" void kernel_launch(void* const* d_in, const int* in_sizes, int n_in,
                              void* d_out, int out_size) {
    const float* x    = (const float*)d_in[0];
    const int*   ei   = (const int*)d_in[1];     // int32 (JAX x64 disabled)
    const float* Wl   = (const float*)d_in[2];
    const float* bl   = (const float*)d_in[3];
    const float* Wr   = (const float*)d_in[4];
    const float* br   = (const float*)d_in[5];
    const float* att  = (const float*)d_in[6];
    const float* bias = (const float*)d_in[7];
    float*       out  = (float*)d_out;

    gemm_count_kernel<<<NBG + NB_CNT, 256>>>(x, Wl, bl, Wr, br, ei);
    csr_kernel<<<NB_CSR, SCAN_B>>>(ei);
    agg_kernel<<<(N_NODES * 32 + 255) / 256, 256>>>(att, bias, out);
}

// round 10
// speedup vs baseline: 1.8254x; 1.1753x over previous
#include <cuda_runtime.h>
#include <cuda_bf16.h>
#include <cstdint>

#define N_NODES 50000
#define N_EDGES 800000
#define CH 128          // HEADS*OUT_CH = 4*32
#define NEG_SLOPE 0.2f
#define SCAN_B 256
#define NB_SCAN ((N_NODES + SCAN_B - 1) / SCAN_B)   // 196
#define NB_CSR 784
#define N_TILES ((N_NODES + 127) / 128)              // 391
#define N_PAD (N_TILES * 128)                        // 50048
#define NB_MMA (N_TILES * 4)                         // 1564: tile x mat x nhalf
// convert+count kernel ranges
#define NB_CVX 3125     // X convert: 3125*256*8 = 6,400,000 floats
#define NB_CVW 16       // W convert: 16*256*8   = 32,768 floats (2 mats)
#define NB_CNT 3125     // count:     3125*256   = 800,000 edges

// ---------------- scratch (static device memory; zero-init at load) ----------
__device__ __align__(16) float g_xl[N_NODES * CH];
__device__ __align__(16) float g_xr[N_NODES * CH];
__device__ __align__(16) uint32_t g_xhi[N_PAD * CH / 2];   // bf16x2 words
__device__ __align__(16) uint32_t g_xlo[N_PAD * CH / 2];
__device__ __align__(16) uint32_t g_whi[2 * CH * CH / 2];
__device__ __align__(16) uint32_t g_wlo[2 * CH * CH / 2];
__device__ int g_cnt[N_NODES];
__device__ int g_off[N_NODES + 1];
__device__ int g_esrc[N_EDGES];
__device__ int g_bsum[NB_SCAN];
__device__ int g_sync1, g_sync2, g_sync3;

// ---------------- helpers -----------------------------------------------------
__device__ __forceinline__ uint32_t smem_u32(const void* p) {
    uint32_t a;
    asm("{ .reg .u64 t; cvta.to.shared.u64 t, %1; cvt.u32.u64 %0, t; }"
        : "=r"(a) : "l"(p));
    return a;
}
// bf16 split of a float pair -> packed hi word + lo word
__device__ __forceinline__ void split2(float a, float b,
                                       uint32_t& hi, uint32_t& lo) {
    __nv_bfloat162 h = __floats2bfloat162_rn(a, b);
    float ra = a - __bfloat162float(h.x);
    float rb = b - __bfloat162float(h.y);
    __nv_bfloat162 l = __floats2bfloat162_rn(ra, rb);
    hi = *(uint32_t*)&h;
    lo = *(uint32_t*)&l;
}
__device__ __forceinline__ void ldsm_x4(uint32_t* r, uint32_t addr) {
    asm volatile("ldmatrix.sync.aligned.m8n8.x4.shared.b16 {%0,%1,%2,%3}, [%4];"
                 : "=r"(r[0]), "=r"(r[1]), "=r"(r[2]), "=r"(r[3]) : "r"(addr));
}
__device__ __forceinline__ void ldsm_x2(uint32_t* r, uint32_t addr) {
    asm volatile("ldmatrix.sync.aligned.m8n8.x2.shared.b16 {%0,%1}, [%2];"
                 : "=r"(r[0]), "=r"(r[1]) : "r"(addr));
}
__device__ __forceinline__ void mma16816(float* d, const uint32_t* a,
                                         const uint32_t* b) {
    asm volatile(
        "mma.sync.aligned.m16n8k16.row.col.f32.bf16.bf16.f32 "
        "{%0,%1,%2,%3}, {%4,%5,%6,%7}, {%8,%9}, {%0,%1,%2,%3};"
        : "+f"(d[0]), "+f"(d[1]), "+f"(d[2]), "+f"(d[3])
        : "r"(a[0]), "r"(a[1]), "r"(a[2]), "r"(a[3]), "r"(b[0]), "r"(b[1]));
}

// ---------------- K1: convert X/W to bf16 hi/lo planes + edge count ----------
__global__ __launch_bounds__(256)
void convert_count_kernel(const float* __restrict__ X,
                          const float* __restrict__ Wl,
                          const float* __restrict__ Wr,
                          const int* __restrict__ ei) {
    const int b = blockIdx.x;
    const int tid = threadIdx.x;
    if (b < NB_CVX) {                       // ---- X split ----
        int p = (b * 256 + tid) * 8;        // float index
        float4 v0 = *(const float4*)(X + p);
        float4 v1 = *(const float4*)(X + p + 4);
        uint4 h, l;
        split2(v0.x, v0.y, h.x, l.x);
        split2(v0.z, v0.w, h.y, l.y);
        split2(v1.x, v1.y, h.z, l.z);
        split2(v1.z, v1.w, h.w, l.w);
        *(uint4*)&g_xhi[p >> 1] = h;
        *(uint4*)&g_xlo[p >> 1] = l;
    } else if (b < NB_CVX + NB_CVW) {       // ---- W split (both mats) ----
        int p = ((b - NB_CVX) * 256 + tid) * 8;   // 0..32767
        const float* W = (p < CH * CH) ? Wl : Wr;
        int q = (p < CH * CH) ? p : p - CH * CH;
        float4 v0 = *(const float4*)(W + q);
        float4 v1 = *(const float4*)(W + q + 4);
        uint4 h, l;
        split2(v0.x, v0.y, h.x, l.x);
        split2(v0.z, v0.w, h.y, l.y);
        split2(v1.x, v1.y, h.z, l.z);
        split2(v1.z, v1.w, h.w, l.w);
        *(uint4*)&g_whi[p >> 1] = h;
        *(uint4*)&g_wlo[p >> 1] = l;
    } else {                                // ---- count ----
        int e = (b - NB_CVX - NB_CVW) * 256 + tid;
        if (e < N_EDGES) atomicAdd(&g_cnt[ei[N_EDGES + e]], 1);
    }
}

// ---------------- K2: bf16x3 HMMA GEMM (mma.sync m16n8k16) -------------------
// Block: 256 thr / 8 warps (4m x 2n), tile 128M x 64N, K=128 in 4 stages of 32.
// smem pitch 40 bf16 (80 B) -> ldmatrix rows hit 8 distinct 16B chunks.
#define PITCH 40
#define A_HL_OFF (128 * PITCH * 2)     // bytes between As hi and lo planes
#define W_HL_OFF (64 * PITCH * 2)

__global__ __launch_bounds__(256)
void gemm_kernel(const float* __restrict__ bl, const float* __restrict__ br) {
    __shared__ __align__(16) uint16_t As[2][128 * PITCH];
    __shared__ __align__(16) uint16_t Ws[2][64 * PITCH];

    const int b    = blockIdx.x;
    const int tile = b >> 2;
    const int mat  = (b >> 1) & 1;
    const int nh   = b & 1;
    const int nb   = tile * 128;
    const int o0   = nh * 64;
    const float* bias = mat ? br : bl;
    float* dst        = mat ? g_xr : g_xl;

    const int tid  = threadIdx.x;
    const int lane = tid & 31;
    const int warp = tid >> 5;
    const int m_warp = (warp & 3) * 32;
    const int n_warp = (warp >> 2) * 32;

    const uint32_t as_base = smem_u32(As);
    const uint32_t ws_base = smem_u32(Ws);

    float acc[2][4][4];
#pragma unroll
    for (int mt = 0; mt < 2; mt++)
#pragma unroll
        for (int nt = 0; nt < 4; nt++)
#pragma unroll
            for (int q = 0; q < 4; q++) acc[mt][nt][q] = 0.f;

    const int arow = lane & 15;
    const int acol8 = (lane >> 4) << 3;
    const int brow = lane & 7;
    const int bcol8 = ((lane >> 3) & 1) << 3;

    for (int kt = 0; kt < CH; kt += 32) {
        // stage A: 128 rows x 32 k (hi+lo)
#pragma unroll
        for (int t = 0; t < 4; t++) {
            int idx = tid + t * 256;             // 0..1023
            int row = idx >> 3;
            int kq  = (idx & 7) << 2;
            int gw  = ((nb + row) * CH + kt + kq) >> 1;
            uint2 vh = *(const uint2*)&g_xhi[gw];
            uint2 vl = *(const uint2*)&g_xlo[gw];
            int sw = (row * PITCH + kq) >> 1;
            *(uint2*)((uint32_t*)As[0] + sw) = vh;
            *(uint2*)((uint32_t*)As[1] + sw) = vl;
        }
        // stage W: 64 rows x 32 k (hi+lo)
#pragma unroll
        for (int t = 0; t < 2; t++) {
            int idx = tid + t * 256;             // 0..511
            int row = idx >> 3;
            int kq  = (idx & 7) << 2;
            int gw  = (mat * CH * CH + (o0 + row) * CH + kt + kq) >> 1;
            uint2 vh = *(const uint2*)&g_whi[gw];
            uint2 vl = *(const uint2*)&g_wlo[gw];
            int sw = (row * PITCH + kq) >> 1;
            *(uint2*)((uint32_t*)Ws[0] + sw) = vh;
            *(uint2*)((uint32_t*)Ws[1] + sw) = vl;
        }
        __syncthreads();

#pragma unroll
        for (int ks = 0; ks < 32; ks += 16) {
            uint32_t ah[2][4], alo[2][4];
#pragma unroll
            for (int mt = 0; mt < 2; mt++) {
                uint32_t adr = as_base +
                    ((m_warp + mt * 16 + arow) * PITCH + ks + acol8) * 2;
                ldsm_x4(ah[mt], adr);
                ldsm_x4(alo[mt], adr + A_HL_OFF);
            }
            uint32_t bh[4][2], blo2[4][2];
#pragma unroll
            for (int nt = 0; nt < 4; nt++) {
                uint32_t adr = ws_base +
                    ((n_warp + nt * 8 + brow) * PITCH + ks + bcol8) * 2;
                ldsm_x2(bh[nt], adr);
                ldsm_x2(blo2[nt], adr + W_HL_OFF);
            }
#pragma unroll
            for (int mt = 0; mt < 2; mt++)
#pragma unroll
                for (int nt = 0; nt < 4; nt++) {
                    mma16816(acc[mt][nt], ah[mt], bh[nt]);
                    mma16816(acc[mt][nt], ah[mt], blo2[nt]);
                    mma16816(acc[mt][nt], alo[mt], bh[nt]);
                }
        }
        __syncthreads();
    }

    // epilogue: d-frag thread t holds (r0,c0),(r0,c0+1),(r0+8,c0),(r0+8,c0+1)
    const int r0 = lane >> 2;
    const int c0 = (lane & 3) << 1;
#pragma unroll
    for (int mt = 0; mt < 2; mt++) {
        int m0 = nb + m_warp + mt * 16 + r0;
#pragma unroll
        for (int nt = 0; nt < 4; nt++) {
            int o = o0 + n_warp + nt * 8 + c0;
            float b0 = __ldg(&bias[o]);
            float b1 = __ldg(&bias[o + 1]);
            if (m0 < N_NODES) {
                float2 r = make_float2(acc[mt][nt][0] + b0, acc[mt][nt][1] + b1);
                *(float2*)(dst + m0 * CH + o) = r;
            }
            if (m0 + 8 < N_NODES) {
                float2 r = make_float2(acc[mt][nt][2] + b0, acc[mt][nt][3] + b1);
                *(float2*)(dst + (m0 + 8) * CH + o) = r;
            }
        }
    }
}

// ---------------- K3: fused scan (2-level) + scatter, spin-wait grid sync ----
__global__ __launch_bounds__(SCAN_B)
void csr_kernel(const int* __restrict__ ei) {
    __shared__ int ws[8];
    __shared__ int s_base;
    const int b    = blockIdx.x;
    const int tid  = threadIdx.x;
    const int lane = tid & 31;
    const int wid  = tid >> 5;

    if (b < NB_SCAN) {
        int idx = b * SCAN_B + tid;
        int v = 0;
        if (idx < N_NODES) { v = g_cnt[idx]; g_cnt[idx] = 0; }
        int s = v;
#pragma unroll
        for (int o = 1; o < 32; o <<= 1) {
            int u = __shfl_up_sync(0xffffffffu, s, o);
            if (lane >= o) s += u;
        }
        if (lane == 31) ws[wid] = s;
        __syncthreads();
        if (wid == 0) {
            int t = (lane < 8) ? ws[lane] : 0;
#pragma unroll
            for (int o = 1; o < 8; o <<= 1) {
                int u = __shfl_up_sync(0xffffffffu, t, o, 8);
                if ((lane & 7) >= o) t += u;
            }
            if (lane < 8) ws[lane] = t;
        }
        __syncthreads();
        int blocksum   = ws[7];
        int local_excl = (wid ? ws[wid - 1] : 0) + s - v;
        __syncthreads();

        if (tid == 0) {
            g_bsum[b] = blocksum;
            __threadfence();
            atomicAdd(&g_sync1, 1);
            while (*(volatile int*)&g_sync1 < NB_SCAN) {}
            __threadfence();
        }
        __syncthreads();

        int pv = (tid < b) ? g_bsum[tid] : 0;
#pragma unroll
        for (int o = 16; o > 0; o >>= 1) pv += __shfl_xor_sync(0xffffffffu, pv, o);
        if (lane == 0) ws[wid] = pv;
        __syncthreads();
        if (tid == 0) {
            int tot = 0;
#pragma unroll
            for (int i = 0; i < 8; i++) tot += ws[i];
            s_base = tot;
        }
        __syncthreads();
        int base = s_base;

        if (idx < N_NODES) g_off[idx] = base + local_excl;
        if (b == NB_SCAN - 1 && tid == 0) g_off[N_NODES] = base + blocksum;

        if (tid == 0) {
            __threadfence();
            atomicAdd(&g_sync2, 1);
        }
    }

    if (tid == 0) {
        while (*(volatile int*)&g_sync2 < NB_SCAN) {}
        __threadfence();
        int t3 = atomicAdd(&g_sync3, 1);
        if (t3 == NB_CSR - 1) { g_sync1 = 0; g_sync2 = 0; g_sync3 = 0; }
    }
    __syncthreads();

    for (int e = b * SCAN_B + tid; e < N_EDGES; e += NB_CSR * SCAN_B) {
        int sp = ei[e];
        int tg = ei[N_EDGES + e];
        int pos = atomicAdd(&g_off[tg], 1);
        g_esrc[pos] = sp;
    }
}

// ---------------- K4: warp-per-node online-softmax aggregation ---------------
__global__ __launch_bounds__(256)
void agg_kernel(const float* __restrict__ att,
                const float* __restrict__ bias,
                float* __restrict__ out) {
    int w    = (blockIdx.x * blockDim.x + threadIdx.x) >> 5;
    int lane = threadIdx.x & 31;
    if (w >= N_NODES) return;
    const int i  = w;
    const int c0 = lane << 2;

    const float4 xlv = *(const float4*)(g_xl + i * CH + c0);
    const float4 av  = *(const float4*)(att + c0);
    const float4 xrs = *(const float4*)(g_xr + i * CH + c0);

    float s0 = xlv.x + xrs.x; s0 = s0 > 0.f ? s0 : NEG_SLOPE * s0;
    float s1 = xlv.y + xrs.y; s1 = s1 > 0.f ? s1 : NEG_SLOPE * s1;
    float s2 = xlv.z + xrs.z; s2 = s2 > 0.f ? s2 : NEG_SLOPE * s2;
    float s3 = xlv.w + xrs.w; s3 = s3 > 0.f ? s3 : NEG_SLOPE * s3;
    float p = av.x * s0 + av.y * s1 + av.z * s2 + av.w * s3;
#pragma unroll
    for (int o = 1; o < 8; o <<= 1) p += __shfl_xor_sync(0xffffffffu, p, o);

    float m = p;
    float d = 1.0f;
    float4 acc = xrs;

    const int beg = i ? __ldg(&g_off[i - 1]) : 0;
    const int end = __ldg(&g_off[i]);

    float4 xv_next = make_float4(0.f, 0.f, 0.f, 0.f);
    if (beg < end) {
        int src0 = __ldg(&g_esrc[beg]);
        xv_next = *(const float4*)(g_xr + src0 * CH + c0);
    }
    for (int e = beg; e < end; e++) {
        float4 xv = xv_next;
        if (e + 1 < end) {
            int sn = __ldg(&g_esrc[e + 1]);
            xv_next = *(const float4*)(g_xr + sn * CH + c0);
        }
        float t0 = xlv.x + xv.x; t0 = t0 > 0.f ? t0 : NEG_SLOPE * t0;
        float t1 = xlv.y + xv.y; t1 = t1 > 0.f ? t1 : NEG_SLOPE * t1;
        float t2 = xlv.z + xv.z; t2 = t2 > 0.f ? t2 : NEG_SLOPE * t2;
        float t3 = xlv.w + xv.w; t3 = t3 > 0.f ? t3 : NEG_SLOPE * t3;
        float q = av.x * t0 + av.y * t1 + av.z * t2 + av.w * t3;
#pragma unroll
        for (int o = 1; o < 8; o <<= 1) q += __shfl_xor_sync(0xffffffffu, q, o);

        float nm = fmaxf(m, q);
        float wm = __expf(m - nm);
        float wq = __expf(q - nm);
        d = d * wm + wq;
        acc.x = acc.x * wm + wq * xv.x;
        acc.y = acc.y * wm + wq * xv.y;
        acc.z = acc.z * wm + wq * xv.z;
        acc.w = acc.w * wm + wq * xv.w;
        m = nm;
    }

    float inv = 1.0f / d;
    const float4 bv = *(const float4*)(bias + c0);
    float4 r = make_float4(acc.x * inv + bv.x, acc.y * inv + bv.y,
                           acc.z * inv + bv.z, acc.w * inv + bv.w);
    *(float4*)(out + i * CH + c0) = r;
}

// ---------------- launch ------------------------------------------------------
extern "C" void kernel_launch(void* const* d_in, const int* in_sizes, int n_in,
                              void* d_out, int out_size) {
    const float* x    = (const float*)d_in[0];
    const int*   ei   = (const int*)d_in[1];     // int32 (JAX x64 disabled)
    const float* Wl   = (const float*)d_in[2];
    const float* bl   = (const float*)d_in[3];
    const float* Wr   = (const float*)d_in[4];
    const float* br   = (const float*)d_in[5];
    const float* att  = (const float*)d_in[6];
    const float* bias = (const float*)d_in[7];
    float*       out  = (float*)d_out;

    convert_count_kernel<<<NB_CVX + NB_CVW + NB_CNT, 256>>>(x, Wl, Wr, ei);
    gemm_kernel<<<NB_MMA, 256>>>(bl, br);
    csr_kernel<<<NB_CSR, SCAN_B>>>(ei);
    agg_kernel<<<(N_NODES * 32 + 255) / 256, 256>>>(att, bias, out);
}

// round 11
// speedup vs baseline: 1.8593x; 1.0186x over previous
#include <cuda_runtime.h>
#include <cuda_bf16.h>
#include <cstdint>

#define N_NODES 50000
#define N_EDGES 800000
#define CH 128          // HEADS*OUT_CH = 4*32
#define SCAN_B 256
#define NB_SCAN ((N_NODES + SCAN_B - 1) / SCAN_B)   // 196
#define NB_CSR 784
#define N_TILES ((N_NODES + 127) / 128)              // 391
#define N_PAD (N_TILES * 128)                        // 50048
#define NB_MMA (N_TILES * 4)                         // 1564: tile x mat x nhalf
#define NB_CVX 3125
#define NB_CVW 16
#define NB_CNT 3125

// ---------------- scratch (static device memory; zero-init at load) ----------
__device__ __align__(16) float g_xl[N_NODES * CH];
__device__ __align__(16) float g_xr[N_NODES * CH];
__device__ __align__(16) uint32_t g_xhi[N_PAD * CH / 2];
__device__ __align__(16) uint32_t g_xlo[N_PAD * CH / 2];
__device__ __align__(16) uint32_t g_whi[2 * CH * CH / 2];
__device__ __align__(16) uint32_t g_wlo[2 * CH * CH / 2];
__device__ int g_cnt[N_NODES];
__device__ int g_off[N_NODES + 1];
__device__ int g_esrc[N_EDGES];
__device__ int g_bsum[NB_SCAN];
__device__ int g_sync1, g_sync2, g_sync3;

// ---------------- helpers -----------------------------------------------------
__device__ __forceinline__ uint32_t smem_u32(const void* p) {
    uint32_t a;
    asm("{ .reg .u64 t; cvta.to.shared.u64 t, %1; cvt.u32.u64 %0, t; }"
        : "=r"(a) : "l"(p));
    return a;
}
__device__ __forceinline__ void split2(float a, float b,
                                       uint32_t& hi, uint32_t& lo) {
    __nv_bfloat162 h = __floats2bfloat162_rn(a, b);
    float ra = a - __bfloat162float(h.x);
    float rb = b - __bfloat162float(h.y);
    __nv_bfloat162 l = __floats2bfloat162_rn(ra, rb);
    hi = *(uint32_t*)&h;
    lo = *(uint32_t*)&l;
}
__device__ __forceinline__ void ldsm_x4(uint32_t* r, uint32_t addr) {
    asm volatile("ldmatrix.sync.aligned.m8n8.x4.shared.b16 {%0,%1,%2,%3}, [%4];"
                 : "=r"(r[0]), "=r"(r[1]), "=r"(r[2]), "=r"(r[3]) : "r"(addr));
}
__device__ __forceinline__ void ldsm_x2(uint32_t* r, uint32_t addr) {
    asm volatile("ldmatrix.sync.aligned.m8n8.x2.shared.b16 {%0,%1}, [%2];"
                 : "=r"(r[0]), "=r"(r[1]) : "r"(addr));
}
__device__ __forceinline__ void mma16816(float* d, const uint32_t* a,
                                         const uint32_t* b) {
    asm volatile(
        "mma.sync.aligned.m16n8k16.row.col.f32.bf16.bf16.f32 "
        "{%0,%1,%2,%3}, {%4,%5,%6,%7}, {%8,%9}, {%0,%1,%2,%3};"
        : "+f"(d[0]), "+f"(d[1]), "+f"(d[2]), "+f"(d[3])
        : "r"(a[0]), "r"(a[1]), "r"(a[2]), "r"(a[3]), "r"(b[0]), "r"(b[1]));
}

// ---------------- K1: convert X/W to bf16 hi/lo planes + edge count ----------
__global__ __launch_bounds__(256)
void convert_count_kernel(const float* __restrict__ X,
                          const float* __restrict__ Wl,
                          const float* __restrict__ Wr,
                          const int* __restrict__ ei) {
    const int b = blockIdx.x;
    const int tid = threadIdx.x;
    if (b < NB_CVX) {
        int p = (b * 256 + tid) * 8;
        float4 v0 = *(const float4*)(X + p);
        float4 v1 = *(const float4*)(X + p + 4);
        uint4 h, l;
        split2(v0.x, v0.y, h.x, l.x);
        split2(v0.z, v0.w, h.y, l.y);
        split2(v1.x, v1.y, h.z, l.z);
        split2(v1.z, v1.w, h.w, l.w);
        *(uint4*)&g_xhi[p >> 1] = h;
        *(uint4*)&g_xlo[p >> 1] = l;
    } else if (b < NB_CVX + NB_CVW) {
        int p = ((b - NB_CVX) * 256 + tid) * 8;
        const float* W = (p < CH * CH) ? Wl : Wr;
        int q = (p < CH * CH) ? p : p - CH * CH;
        float4 v0 = *(const float4*)(W + q);
        float4 v1 = *(const float4*)(W + q + 4);
        uint4 h, l;
        split2(v0.x, v0.y, h.x, l.x);
        split2(v0.z, v0.w, h.y, l.y);
        split2(v1.x, v1.y, h.z, l.z);
        split2(v1.z, v1.w, h.w, l.w);
        *(uint4*)&g_whi[p >> 1] = h;
        *(uint4*)&g_wlo[p >> 1] = l;
    } else {
        int e = (b - NB_CVX - NB_CVW) * 256 + tid;
        if (e < N_EDGES) atomicAdd(&g_cnt[ei[N_EDGES + e]], 1);
    }
}

// ---------------- K2: fused CSR build + bf16x3 HMMA GEMM ---------------------
// Blocks [0, NB_CSR): scan (blocks 0..195, co-resident in wave 1) + scatter.
// Blocks [NB_CSR, NB_CSR+NB_MMA): GEMM (independent of csr work).
#define PITCH 40
#define A_HL_OFF (128 * PITCH * 2)
#define W_HL_OFF (64 * PITCH * 2)

__global__ __launch_bounds__(256)
void csr_gemm_kernel(const int* __restrict__ ei,
                     const float* __restrict__ bl,
                     const float* __restrict__ br) {
    const int tid  = threadIdx.x;
    const int lane = tid & 31;

    if (blockIdx.x < NB_CSR) {             // ================= CSR path =======
        __shared__ int ws[8];
        __shared__ int s_base;
        const int b   = blockIdx.x;
        const int wid = tid >> 5;

        if (b < NB_SCAN) {
            int idx = b * SCAN_B + tid;
            int v = 0;
            if (idx < N_NODES) { v = g_cnt[idx]; g_cnt[idx] = 0; }
            int s = v;
#pragma unroll
            for (int o = 1; o < 32; o <<= 1) {
                int u = __shfl_up_sync(0xffffffffu, s, o);
                if (lane >= o) s += u;
            }
            if (lane == 31) ws[wid] = s;
            __syncthreads();
            if (wid == 0) {
                int t = (lane < 8) ? ws[lane] : 0;
#pragma unroll
                for (int o = 1; o < 8; o <<= 1) {
                    int u = __shfl_up_sync(0xffffffffu, t, o, 8);
                    if ((lane & 7) >= o) t += u;
                }
                if (lane < 8) ws[lane] = t;
            }
            __syncthreads();
            int blocksum   = ws[7];
            int local_excl = (wid ? ws[wid - 1] : 0) + s - v;
            __syncthreads();

            if (tid == 0) {
                g_bsum[b] = blocksum;
                __threadfence();
                atomicAdd(&g_sync1, 1);
                while (*(volatile int*)&g_sync1 < NB_SCAN) {}
                __threadfence();
            }
            __syncthreads();

            int pv = (tid < b) ? g_bsum[tid] : 0;
#pragma unroll
            for (int o = 16; o > 0; o >>= 1)
                pv += __shfl_xor_sync(0xffffffffu, pv, o);
            if (lane == 0) ws[wid] = pv;
            __syncthreads();
            if (tid == 0) {
                int tot = 0;
#pragma unroll
                for (int i = 0; i < 8; i++) tot += ws[i];
                s_base = tot;
            }
            __syncthreads();
            int base = s_base;

            if (idx < N_NODES) g_off[idx] = base + local_excl;
            if (b == NB_SCAN - 1 && tid == 0) g_off[N_NODES] = base + blocksum;

            if (tid == 0) {
                __threadfence();
                atomicAdd(&g_sync2, 1);
            }
        }

        if (tid == 0) {
            while (*(volatile int*)&g_sync2 < NB_SCAN) {}
            __threadfence();
            int t3 = atomicAdd(&g_sync3, 1);
            if (t3 == NB_CSR - 1) { g_sync1 = 0; g_sync2 = 0; g_sync3 = 0; }
        }
        __syncthreads();

        for (int e = b * SCAN_B + tid; e < N_EDGES; e += NB_CSR * SCAN_B) {
            int sp = ei[e];
            int tg = ei[N_EDGES + e];
            int pos = atomicAdd(&g_off[tg], 1);
            g_esrc[pos] = sp;
        }
        return;
    }

    // ================= GEMM path =============================================
    __shared__ __align__(16) uint16_t As[2][128 * PITCH];
    __shared__ __align__(16) uint16_t Ws[2][64 * PITCH];

    const int b    = blockIdx.x - NB_CSR;
    const int tile = b >> 2;
    const int mat  = (b >> 1) & 1;
    const int nh   = b & 1;
    const int nb   = tile * 128;
    const int o0   = nh * 64;
    const float* bias = mat ? br : bl;
    float* dst        = mat ? g_xr : g_xl;

    const int warp = tid >> 5;
    const int m_warp = (warp & 3) * 32;
    const int n_warp = (warp >> 2) * 32;

    const uint32_t as_base = smem_u32(As);
    const uint32_t ws_base = smem_u32(Ws);

    float acc[2][4][4];
#pragma unroll
    for (int mt = 0; mt < 2; mt++)
#pragma unroll
        for (int nt = 0; nt < 4; nt++)
#pragma unroll
            for (int q = 0; q < 4; q++) acc[mt][nt][q] = 0.f;

    const int arow = lane & 15;
    const int acol8 = (lane >> 4) << 3;
    const int brow = lane & 7;
    const int bcol8 = ((lane >> 3) & 1) << 3;

    for (int kt = 0; kt < CH; kt += 32) {
#pragma unroll
        for (int t = 0; t < 4; t++) {
            int idx = tid + t * 256;
            int row = idx >> 3;
            int kq  = (idx & 7) << 2;
            int gw  = ((nb + row) * CH + kt + kq) >> 1;
            uint2 vh = *(const uint2*)&g_xhi[gw];
            uint2 vl = *(const uint2*)&g_xlo[gw];
            int sw = (row * PITCH + kq) >> 1;
            *(uint2*)((uint32_t*)As[0] + sw) = vh;
            *(uint2*)((uint32_t*)As[1] + sw) = vl;
        }
#pragma unroll
        for (int t = 0; t < 2; t++) {
            int idx = tid + t * 256;
            int row = idx >> 3;
            int kq  = (idx & 7) << 2;
            int gw  = (mat * CH * CH + (o0 + row) * CH + kt + kq) >> 1;
            uint2 vh = *(const uint2*)&g_whi[gw];
            uint2 vl = *(const uint2*)&g_wlo[gw];
            int sw = (row * PITCH + kq) >> 1;
            *(uint2*)((uint32_t*)Ws[0] + sw) = vh;
            *(uint2*)((uint32_t*)Ws[1] + sw) = vl;
        }
        __syncthreads();

#pragma unroll
        for (int ks = 0; ks < 32; ks += 16) {
            uint32_t ah[2][4], alo[2][4];
#pragma unroll
            for (int mt = 0; mt < 2; mt++) {
                uint32_t adr = as_base +
                    ((m_warp + mt * 16 + arow) * PITCH + ks + acol8) * 2;
                ldsm_x4(ah[mt], adr);
                ldsm_x4(alo[mt], adr + A_HL_OFF);
            }
            uint32_t bh[4][2], blo2[4][2];
#pragma unroll
            for (int nt = 0; nt < 4; nt++) {
                uint32_t adr = ws_base +
                    ((n_warp + nt * 8 + brow) * PITCH + ks + bcol8) * 2;
                ldsm_x2(bh[nt], adr);
                ldsm_x2(blo2[nt], adr + W_HL_OFF);
            }
#pragma unroll
            for (int mt = 0; mt < 2; mt++)
#pragma unroll
                for (int nt = 0; nt < 4; nt++) {
                    mma16816(acc[mt][nt], ah[mt], bh[nt]);
                    mma16816(acc[mt][nt], ah[mt], blo2[nt]);
                    mma16816(acc[mt][nt], alo[mt], bh[nt]);
                }
        }
        __syncthreads();
    }

    const int r0 = lane >> 2;
    const int c0 = (lane & 3) << 1;
#pragma unroll
    for (int mt = 0; mt < 2; mt++) {
        int m0 = nb + m_warp + mt * 16 + r0;
#pragma unroll
        for (int nt = 0; nt < 4; nt++) {
            int o = o0 + n_warp + nt * 8 + c0;
            float b0 = __ldg(&bias[o]);
            float b1 = __ldg(&bias[o + 1]);
            if (m0 < N_NODES) {
                float2 r = make_float2(acc[mt][nt][0] + b0, acc[mt][nt][1] + b1);
                *(float2*)(dst + m0 * CH + o) = r;
            }
            if (m0 + 8 < N_NODES) {
                float2 r = make_float2(acc[mt][nt][2] + b0, acc[mt][nt][3] + b1);
                *(float2*)(dst + (m0 + 8) * CH + o) = r;
            }
        }
    }
}

// ---------------- K3: warp-per-node online-softmax, 8-edge batched -----------
// leaky(s) = 0.6s + 0.4|s| (NEG_SLOPE=0.2), folded into scaled att vectors.
__global__ __launch_bounds__(256)
void agg_kernel(const float* __restrict__ att,
                const float* __restrict__ bias,
                float* __restrict__ out) {
    int w    = (blockIdx.x * blockDim.x + threadIdx.x) >> 5;
    int lane = threadIdx.x & 31;
    if (w >= N_NODES) return;
    const int i  = w;
    const int c0 = lane << 2;

    const float4 xlv = *(const float4*)(g_xl + i * CH + c0);
    const float4 av  = *(const float4*)(att + c0);
    const float4 xrs = *(const float4*)(g_xr + i * CH + c0);
    const float4 a6 = make_float4(0.6f * av.x, 0.6f * av.y,
                                  0.6f * av.z, 0.6f * av.w);
    const float4 a4 = make_float4(0.4f * av.x, 0.4f * av.y,
                                  0.4f * av.z, 0.4f * av.w);

    // self-loop logit
    {
        float s0 = xlv.x + xrs.x, s1 = xlv.y + xrs.y;
        float s2 = xlv.z + xrs.z, s3 = xlv.w + xrs.w;
        float p = a6.x * s0 + a4.x * fabsf(s0);
        p += a6.y * s1 + a4.y * fabsf(s1);
        p += a6.z * s2 + a4.z * fabsf(s2);
        p += a6.w * s3 + a4.w * fabsf(s3);
#pragma unroll
        for (int o = 1; o < 8; o <<= 1) p += __shfl_xor_sync(0xffffffffu, p, o);
        // init running state
        float m = p;
        float d = 1.0f;
        float4 acc = xrs;

        int e = i ? __ldg(&g_off[i - 1]) : 0;
        const int end = __ldg(&g_off[i]);

        // ---- 8-edge batches ----
        for (; e + 8 <= end; e += 8) {
            float4 xv[8];
#pragma unroll
            for (int j = 0; j < 8; j++) {
                int src = __ldg(&g_esrc[e + j]);
                xv[j] = *(const float4*)(g_xr + src * CH + c0);
            }
            float pj[8];
#pragma unroll
            for (int j = 0; j < 8; j++) {
                float t0 = xlv.x + xv[j].x;
                float t1 = xlv.y + xv[j].y;
                float t2 = xlv.z + xv[j].z;
                float t3 = xlv.w + xv[j].w;
                float q = a6.x * t0 + a4.x * fabsf(t0);
                q += a6.y * t1 + a4.y * fabsf(t1);
                q += a6.z * t2 + a4.z * fabsf(t2);
                q += a6.w * t3 + a4.w * fabsf(t3);
                pj[j] = q;
            }
            // butterfly transpose-reduce across 8-lane head groups:
            // after 3 steps lane (g*8+j) holds logit of edge e+j for head g
            {
                bool b0 = lane & 1;
#pragma unroll
                for (int k = 0; k < 4; k++) {
                    float snd = b0 ? pj[2 * k] : pj[2 * k + 1];
                    float kp  = b0 ? pj[2 * k + 1] : pj[2 * k];
                    pj[k] = kp + __shfl_xor_sync(0xffffffffu, snd, 1);
                }
                bool b1 = lane & 2;
#pragma unroll
                for (int k = 0; k < 2; k++) {
                    float snd = b1 ? pj[2 * k] : pj[2 * k + 1];
                    float kp  = b1 ? pj[2 * k + 1] : pj[2 * k];
                    pj[k] = kp + __shfl_xor_sync(0xffffffffu, snd, 2);
                }
                bool b2 = lane & 4;
                {
                    float snd = b2 ? pj[0] : pj[1];
                    float kp  = b2 ? pj[1] : pj[0];
                    pj[0] = kp + __shfl_xor_sync(0xffffffffu, snd, 4);
                }
            }
            float q = pj[0];
            // per-head max of the 8 logits
            float qm = q;
            qm = fmaxf(qm, __shfl_xor_sync(0xffffffffu, qm, 1));
            qm = fmaxf(qm, __shfl_xor_sync(0xffffffffu, qm, 2));
            qm = fmaxf(qm, __shfl_xor_sync(0xffffffffu, qm, 4));
            float nm = fmaxf(m, qm);
            float wq = __expf(q - nm);
            float wm = __expf(m - nm);
            m = nm;
            // allgather edge weights within the head group
            float wv[8];
            int gbase = lane & 24;
#pragma unroll
            for (int j = 0; j < 8; j++)
                wv[j] = __shfl_sync(0xffffffffu, wq, gbase + j);
            float dsum = ((wv[0] + wv[1]) + (wv[2] + wv[3])) +
                         ((wv[4] + wv[5]) + (wv[6] + wv[7]));
            d = d * wm + dsum;
            acc.x *= wm; acc.y *= wm; acc.z *= wm; acc.w *= wm;
#pragma unroll
            for (int j = 0; j < 8; j++) {
                acc.x += wv[j] * xv[j].x;
                acc.y += wv[j] * xv[j].y;
                acc.z += wv[j] * xv[j].z;
                acc.w += wv[j] * xv[j].w;
            }
        }

        // ---- remainder (scalar path) ----
        for (; e < end; e++) {
            int src = __ldg(&g_esrc[e]);
            float4 xv = *(const float4*)(g_xr + src * CH + c0);
            float t0 = xlv.x + xv.x;
            float t1 = xlv.y + xv.y;
            float t2 = xlv.z + xv.z;
            float t3 = xlv.w + xv.w;
            float q = a6.x * t0 + a4.x * fabsf(t0);
            q += a6.y * t1 + a4.y * fabsf(t1);
            q += a6.z * t2 + a4.z * fabsf(t2);
            q += a6.w * t3 + a4.w * fabsf(t3);
#pragma unroll
            for (int o = 1; o < 8; o <<= 1)
                q += __shfl_xor_sync(0xffffffffu, q, o);

            float nm = fmaxf(m, q);
            float wm = __expf(m - nm);
            float wq = __expf(q - nm);
            d = d * wm + wq;
            acc.x = acc.x * wm + wq * xv.x;
            acc.y = acc.y * wm + wq * xv.y;
            acc.z = acc.z * wm + wq * xv.z;
            acc.w = acc.w * wm + wq * xv.w;
            m = nm;
        }

        float inv = 1.0f / d;
        const float4 bv = *(const float4*)(bias + c0);
        float4 r = make_float4(acc.x * inv + bv.x, acc.y * inv + bv.y,
                               acc.z * inv + bv.z, acc.w * inv + bv.w);
        *(float4*)(out + i * CH + c0) = r;
    }
}

// ---------------- launch ------------------------------------------------------
extern "C" void kernel_launch(void* const* d_in, const int* in_sizes, int n_in,
                              void* d_out, int out_size) {
    const float* x    = (const float*)d_in[0];
    const int*   ei   = (const int*)d_in[1];     // int32 (JAX x64 disabled)
    const float* Wl   = (const float*)d_in[2];
    const float* bl   = (const float*)d_in[3];
    const float* Wr   = (const float*)d_in[4];
    const float* br   = (const float*)d_in[5];
    const float* att  = (const float*)d_in[6];
    const float* bias = (const float*)d_in[7];
    float*       out  = (float*)d_out;

    convert_count_kernel<<<NB_CVX + NB_CVW + NB_CNT, 256>>>(x, Wl, Wr, ei);
    csr_gemm_kernel<<<NB_CSR + NB_MMA, 256>>>(ei, bl, br);
    agg_kernel<<<(N_NODES * 32 + 255) / 256, 256>>>(att, bias, out);
}

// round 12
// speedup vs baseline: 2.1322x; 1.1468x over previous
#include <cuda_runtime.h>
#include <cuda_bf16.h>
#include <cstdint>

#define N_NODES 50000
#define N_EDGES 800000
#define CH 128          // HEADS*OUT_CH = 4*32
#define SCAN_B 256
#define NB_SCAN ((N_NODES + SCAN_B - 1) / SCAN_B)   // 196
#define N_TILES ((N_NODES + 127) / 128)              // 391
#define NB_MMA (N_TILES * 4)                         // 1564: tile x mat x nhalf

// ---------------- scratch (static device memory; zero-init at load) ----------
__device__ __align__(16) float g_xl[N_NODES * CH];
__device__ __align__(16) float g_xr[N_NODES * CH];
__device__ int g_cnt[N_NODES];        // zero-init; consumed+re-zeroed in-kernel
__device__ int g_off[N_NODES + 1];
__device__ int g_esrc[N_EDGES];
__device__ int g_bsum[NB_SCAN];
__device__ int g_sync0, g_sync1, g_sync2, g_sync3;   // self-resetting counters

// ---------------- helpers -----------------------------------------------------
__device__ __forceinline__ uint32_t smem_u32(const void* p) {
    uint32_t a;
    asm("{ .reg .u64 t; cvta.to.shared.u64 t, %1; cvt.u32.u64 %0, t; }"
        : "=r"(a) : "l"(p));
    return a;
}
// bf16 split of a float pair -> packed hi word + lo word
__device__ __forceinline__ void split2(float a, float b,
                                       uint32_t& hi, uint32_t& lo) {
    __nv_bfloat162 h = __floats2bfloat162_rn(a, b);
    float ra = a - __bfloat162float(h.x);
    float rb = b - __bfloat162float(h.y);
    __nv_bfloat162 l = __floats2bfloat162_rn(ra, rb);
    hi = *(uint32_t*)&h;
    lo = *(uint32_t*)&l;
}
__device__ __forceinline__ void ldsm_x4(uint32_t* r, uint32_t addr) {
    asm volatile("ldmatrix.sync.aligned.m8n8.x4.shared.b16 {%0,%1,%2,%3}, [%4];"
                 : "=r"(r[0]), "=r"(r[1]), "=r"(r[2]), "=r"(r[3]) : "r"(addr));
}
__device__ __forceinline__ void ldsm_x2(uint32_t* r, uint32_t addr) {
    asm volatile("ldmatrix.sync.aligned.m8n8.x2.shared.b16 {%0,%1}, [%2];"
                 : "=r"(r[0]), "=r"(r[1]) : "r"(addr));
}
__device__ __forceinline__ void mma16816(float* d, const uint32_t* a,
                                         const uint32_t* b) {
    asm volatile(
        "mma.sync.aligned.m16n8k16.row.col.f32.bf16.bf16.f32 "
        "{%0,%1,%2,%3}, {%4,%5,%6,%7}, {%8,%9}, {%0,%1,%2,%3};"
        : "+f"(d[0]), "+f"(d[1]), "+f"(d[2]), "+f"(d[3])
        : "r"(a[0]), "r"(a[1]), "r"(a[2]), "r"(a[3]), "r"(b[0]), "r"(b[1]));
}

// ---------------- K1: fused CSR build (196 blocks) + bf16x3 HMMA GEMM --------
// Blocks [0, NB_SCAN): count -> barrier -> scan -> barrier -> scatter.
// All barriers are all-arrive among these 196 FIRST-SCHEDULED blocks only.
// Blocks [NB_SCAN, NB_SCAN+NB_MMA): GEMM, stages fp32 X/W with in-flight
// bf16 hi/lo split (no global bf16 staging buffers at all).
#define PITCH 40
#define A_HL_OFF (128 * PITCH * 2)
#define W_HL_OFF (64 * PITCH * 2)

__global__ __launch_bounds__(256)
void csr_gemm_kernel(const float* __restrict__ X,
                     const int* __restrict__ ei,
                     const float* __restrict__ Wl, const float* __restrict__ bl,
                     const float* __restrict__ Wr, const float* __restrict__ br) {
    const int tid  = threadIdx.x;
    const int lane = tid & 31;

    if (blockIdx.x < NB_SCAN) {            // ================= CSR path =======
        __shared__ int ws[8];
        __shared__ int s_base;
        const int b   = blockIdx.x;
        const int wid = tid >> 5;

        // ---- count (grid-stride over edges by the 196 scan blocks) ----
        for (int e = b * SCAN_B + tid; e < N_EDGES; e += NB_SCAN * SCAN_B)
            atomicAdd(&g_cnt[ei[N_EDGES + e]], 1);
        __threadfence();
        __syncthreads();
        if (tid == 0) {
            atomicAdd(&g_sync0, 1);
            while (*(volatile int*)&g_sync0 < NB_SCAN) {}
            __threadfence();
        }
        __syncthreads();

        // ---- block-local scan (consume + re-zero g_cnt) ----
        int idx = b * SCAN_B + tid;
        int v = 0;
        if (idx < N_NODES) { v = g_cnt[idx]; g_cnt[idx] = 0; }
        int s = v;
#pragma unroll
        for (int o = 1; o < 32; o <<= 1) {
            int u = __shfl_up_sync(0xffffffffu, s, o);
            if (lane >= o) s += u;
        }
        if (lane == 31) ws[wid] = s;
        __syncthreads();
        if (wid == 0) {
            int t = (lane < 8) ? ws[lane] : 0;
#pragma unroll
            for (int o = 1; o < 8; o <<= 1) {
                int u = __shfl_up_sync(0xffffffffu, t, o, 8);
                if ((lane & 7) >= o) t += u;
            }
            if (lane < 8) ws[lane] = t;
        }
        __syncthreads();
        int blocksum   = ws[7];
        int local_excl = (wid ? ws[wid - 1] : 0) + s - v;
        __syncthreads();

        if (tid == 0) {
            g_bsum[b] = blocksum;
            __threadfence();
            atomicAdd(&g_sync1, 1);
            while (*(volatile int*)&g_sync1 < NB_SCAN) {}
            __threadfence();
        }
        __syncthreads();

        // prefix over preceding block sums (196 < 256 threads)
        int pv = (tid < b) ? g_bsum[tid] : 0;
#pragma unroll
        for (int o = 16; o > 0; o >>= 1)
            pv += __shfl_xor_sync(0xffffffffu, pv, o);
        if (lane == 0) ws[wid] = pv;
        __syncthreads();
        if (tid == 0) {
            int tot = 0;
#pragma unroll
            for (int i = 0; i < 8; i++) tot += ws[i];
            s_base = tot;
        }
        __syncthreads();
        int base = s_base;

        if (idx < N_NODES) g_off[idx] = base + local_excl;
        if (b == NB_SCAN - 1 && tid == 0) g_off[N_NODES] = base + blocksum;

        if (tid == 0) {
            __threadfence();
            atomicAdd(&g_sync2, 1);
            while (*(volatile int*)&g_sync2 < NB_SCAN) {}
            __threadfence();
            int t3 = atomicAdd(&g_sync3, 1);
            if (t3 == NB_SCAN - 1) {
                g_sync0 = 0; g_sync1 = 0; g_sync2 = 0; g_sync3 = 0;
            }
        }
        __syncthreads();

        // ---- scatter (bump g_off[t]: post-scatter g_off[i] == end of i) ----
        for (int e = b * SCAN_B + tid; e < N_EDGES; e += NB_SCAN * SCAN_B) {
            int sp = ei[e];
            int tg = ei[N_EDGES + e];
            int pos = atomicAdd(&g_off[tg], 1);
            g_esrc[pos] = sp;
        }
        return;
    }

    // ================= GEMM path =============================================
    __shared__ __align__(16) uint16_t As[2][128 * PITCH];
    __shared__ __align__(16) uint16_t Ws[2][64 * PITCH];

    const int gb   = blockIdx.x - NB_SCAN;
    const int tile = gb >> 2;
    const int mat  = (gb >> 1) & 1;
    const int nh   = gb & 1;
    const int nb   = tile * 128;
    const int o0   = nh * 64;
    const float* W    = mat ? Wr : Wl;
    const float* bias = mat ? br : bl;
    float* dst        = mat ? g_xr : g_xl;

    const int warp = tid >> 5;
    const int m_warp = (warp & 3) * 32;
    const int n_warp = (warp >> 2) * 32;

    const uint32_t as_base = smem_u32(As);
    const uint32_t ws_base = smem_u32(Ws);

    float acc[2][4][4];
#pragma unroll
    for (int mt = 0; mt < 2; mt++)
#pragma unroll
        for (int nt = 0; nt < 4; nt++)
#pragma unroll
            for (int q = 0; q < 4; q++) acc[mt][nt][q] = 0.f;

    const int arow = lane & 15;
    const int acol8 = (lane >> 4) << 3;
    const int brow = lane & 7;
    const int bcol8 = ((lane >> 3) & 1) << 3;

    for (int kt = 0; kt < CH; kt += 32) {
        // stage A from fp32 X with in-flight bf16 split: 128 rows x 32 k
#pragma unroll
        for (int t = 0; t < 4; t++) {
            int idx = tid + t * 256;             // 0..1023
            int row = idx >> 3;
            int kq  = (idx & 7) << 2;
            int gn  = nb + row;
            float4 v = make_float4(0.f, 0.f, 0.f, 0.f);
            if (gn < N_NODES) v = *(const float4*)(X + gn * CH + kt + kq);
            uint32_t h0, l0, h1, l1;
            split2(v.x, v.y, h0, l0);
            split2(v.z, v.w, h1, l1);
            int sw = (row * PITCH + kq) >> 1;
            ((uint32_t*)As[0])[sw]     = h0;
            ((uint32_t*)As[0])[sw + 1] = h1;
            ((uint32_t*)As[1])[sw]     = l0;
            ((uint32_t*)As[1])[sw + 1] = l1;
        }
        // stage W from fp32 with in-flight split: 64 rows x 32 k
#pragma unroll
        for (int t = 0; t < 2; t++) {
            int idx = tid + t * 256;             // 0..511
            int row = idx >> 3;
            int kq  = (idx & 7) << 2;
            float4 v = *(const float4*)(W + (o0 + row) * CH + kt + kq);
            uint32_t h0, l0, h1, l1;
            split2(v.x, v.y, h0, l0);
            split2(v.z, v.w, h1, l1);
            int sw = (row * PITCH + kq) >> 1;
            ((uint32_t*)Ws[0])[sw]     = h0;
            ((uint32_t*)Ws[0])[sw + 1] = h1;
            ((uint32_t*)Ws[1])[sw]     = l0;
            ((uint32_t*)Ws[1])[sw + 1] = l1;
        }
        __syncthreads();

#pragma unroll
        for (int ks = 0; ks < 32; ks += 16) {
            uint32_t ah[2][4], alo[2][4];
#pragma unroll
            for (int mt = 0; mt < 2; mt++) {
                uint32_t adr = as_base +
                    ((m_warp + mt * 16 + arow) * PITCH + ks + acol8) * 2;
                ldsm_x4(ah[mt], adr);
                ldsm_x4(alo[mt], adr + A_HL_OFF);
            }
            uint32_t bh[4][2], blo2[4][2];
#pragma unroll
            for (int nt = 0; nt < 4; nt++) {
                uint32_t adr = ws_base +
                    ((n_warp + nt * 8 + brow) * PITCH + ks + bcol8) * 2;
                ldsm_x2(bh[nt], adr);
                ldsm_x2(blo2[nt], adr + W_HL_OFF);
            }
#pragma unroll
            for (int mt = 0; mt < 2; mt++)
#pragma unroll
                for (int nt = 0; nt < 4; nt++) {
                    mma16816(acc[mt][nt], ah[mt], bh[nt]);
                    mma16816(acc[mt][nt], ah[mt], blo2[nt]);
                    mma16816(acc[mt][nt], alo[mt], bh[nt]);
                }
        }
        __syncthreads();
    }

    const int r0 = lane >> 2;
    const int c0 = (lane & 3) << 1;
#pragma unroll
    for (int mt = 0; mt < 2; mt++) {
        int m0 = nb + m_warp + mt * 16 + r0;
#pragma unroll
        for (int nt = 0; nt < 4; nt++) {
            int o = o0 + n_warp + nt * 8 + c0;
            float b0 = __ldg(&bias[o]);
            float b1 = __ldg(&bias[o + 1]);
            if (m0 < N_NODES) {
                float2 r = make_float2(acc[mt][nt][0] + b0, acc[mt][nt][1] + b1);
                *(float2*)(dst + m0 * CH + o) = r;
            }
            if (m0 + 8 < N_NODES) {
                float2 r = make_float2(acc[mt][nt][2] + b0, acc[mt][nt][3] + b1);
                *(float2*)(dst + (m0 + 8) * CH + o) = r;
            }
        }
    }
}

// ---------------- K2: warp-per-node online-softmax, 8-edge batched -----------
// leaky(s) = 0.6s + 0.4|s| (NEG_SLOPE=0.2), folded into scaled att vectors.
__global__ __launch_bounds__(256)
void agg_kernel(const float* __restrict__ att,
                const float* __restrict__ bias,
                float* __restrict__ out) {
    int w    = (blockIdx.x * blockDim.x + threadIdx.x) >> 5;
    int lane = threadIdx.x & 31;
    if (w >= N_NODES) return;
    const int i  = w;
    const int c0 = lane << 2;

    const float4 xlv = *(const float4*)(g_xl + i * CH + c0);
    const float4 av  = *(const float4*)(att + c0);
    const float4 xrs = *(const float4*)(g_xr + i * CH + c0);
    const float4 a6 = make_float4(0.6f * av.x, 0.6f * av.y,
                                  0.6f * av.z, 0.6f * av.w);
    const float4 a4 = make_float4(0.4f * av.x, 0.4f * av.y,
                                  0.4f * av.z, 0.4f * av.w);

    float s0 = xlv.x + xrs.x, s1 = xlv.y + xrs.y;
    float s2 = xlv.z + xrs.z, s3 = xlv.w + xrs.w;
    float p = a6.x * s0 + a4.x * fabsf(s0);
    p += a6.y * s1 + a4.y * fabsf(s1);
    p += a6.z * s2 + a4.z * fabsf(s2);
    p += a6.w * s3 + a4.w * fabsf(s3);
#pragma unroll
    for (int o = 1; o < 8; o <<= 1) p += __shfl_xor_sync(0xffffffffu, p, o);

    float m = p;
    float d = 1.0f;
    float4 acc = xrs;

    int e = i ? __ldg(&g_off[i - 1]) : 0;
    const int end = __ldg(&g_off[i]);

    // ---- 8-edge batches ----
    for (; e + 8 <= end; e += 8) {
        float4 xv[8];
#pragma unroll
        for (int j = 0; j < 8; j++) {
            int src = __ldg(&g_esrc[e + j]);
            xv[j] = *(const float4*)(g_xr + src * CH + c0);
        }
        float pj[8];
#pragma unroll
        for (int j = 0; j < 8; j++) {
            float t0 = xlv.x + xv[j].x;
            float t1 = xlv.y + xv[j].y;
            float t2 = xlv.z + xv[j].z;
            float t3 = xlv.w + xv[j].w;
            float q = a6.x * t0 + a4.x * fabsf(t0);
            q += a6.y * t1 + a4.y * fabsf(t1);
            q += a6.z * t2 + a4.z * fabsf(t2);
            q += a6.w * t3 + a4.w * fabsf(t3);
            pj[j] = q;
        }
        // butterfly transpose-reduce: lane (g*8+j) ends with edge j, head g
        {
            bool b0 = lane & 1;
#pragma unroll
            for (int k = 0; k < 4; k++) {
                float snd = b0 ? pj[2 * k] : pj[2 * k + 1];
                float kp  = b0 ? pj[2 * k + 1] : pj[2 * k];
                pj[k] = kp + __shfl_xor_sync(0xffffffffu, snd, 1);
            }
            bool b1 = lane & 2;
#pragma unroll
            for (int k = 0; k < 2; k++) {
                float snd = b1 ? pj[2 * k] : pj[2 * k + 1];
                float kp  = b1 ? pj[2 * k + 1] : pj[2 * k];
                pj[k] = kp + __shfl_xor_sync(0xffffffffu, snd, 2);
            }
            bool b2 = lane & 4;
            {
                float snd = b2 ? pj[0] : pj[1];
                float kp  = b2 ? pj[1] : pj[0];
                pj[0] = kp + __shfl_xor_sync(0xffffffffu, snd, 4);
            }
        }
        float q = pj[0];
        float qm = q;
        qm = fmaxf(qm, __shfl_xor_sync(0xffffffffu, qm, 1));
        qm = fmaxf(qm, __shfl_xor_sync(0xffffffffu, qm, 2));
        qm = fmaxf(qm, __shfl_xor_sync(0xffffffffu, qm, 4));
        float nm = fmaxf(m, qm);
        float wq = __expf(q - nm);
        float wm = __expf(m - nm);
        m = nm;
        float wv[8];
        int gbase = lane & 24;
#pragma unroll
        for (int j = 0; j < 8; j++)
            wv[j] = __shfl_sync(0xffffffffu, wq, gbase + j);
        float dsum = ((wv[0] + wv[1]) + (wv[2] + wv[3])) +
                     ((wv[4] + wv[5]) + (wv[6] + wv[7]));
        d = d * wm + dsum;
        acc.x *= wm; acc.y *= wm; acc.z *= wm; acc.w *= wm;
#pragma unroll
        for (int j = 0; j < 8; j++) {
            acc.x += wv[j] * xv[j].x;
            acc.y += wv[j] * xv[j].y;
            acc.z += wv[j] * xv[j].z;
            acc.w += wv[j] * xv[j].w;
        }
    }

    // ---- remainder ----
    for (; e < end; e++) {
        int src = __ldg(&g_esrc[e]);
        float4 xv = *(const float4*)(g_xr + src * CH + c0);
        float t0 = xlv.x + xv.x;
        float t1 = xlv.y + xv.y;
        float t2 = xlv.z + xv.z;
        float t3 = xlv.w + xv.w;
        float q = a6.x * t0 + a4.x * fabsf(t0);
        q += a6.y * t1 + a4.y * fabsf(t1);
        q += a6.z * t2 + a4.z * fabsf(t2);
        q += a6.w * t3 + a4.w * fabsf(t3);
#pragma unroll
        for (int o = 1; o < 8; o <<= 1)
            q += __shfl_xor_sync(0xffffffffu, q, o);

        float nm = fmaxf(m, q);
        float wm = __expf(m - nm);
        float wq = __expf(q - nm);
        d = d * wm + wq;
        acc.x = acc.x * wm + wq * xv.x;
        acc.y = acc.y * wm + wq * xv.y;
        acc.z = acc.z * wm + wq * xv.z;
        acc.w = acc.w * wm + wq * xv.w;
        m = nm;
    }

    float inv = 1.0f / d;
    const float4 bv = *(const float4*)(bias + c0);
    float4 r = make_float4(acc.x * inv + bv.x, acc.y * inv + bv.y,
                           acc.z * inv + bv.z, acc.w * inv + bv.w);
    *(float4*)(out + i * CH + c0) = r;
}

// ---------------- launch ------------------------------------------------------
extern "C" void kernel_launch(void* const* d_in, const int* in_sizes, int n_in,
                              void* d_out, int out_size) {
    const float* x    = (const float*)d_in[0];
    const int*   ei   = (const int*)d_in[1];     // int32 (JAX x64 disabled)
    const float* Wl   = (const float*)d_in[2];
    const float* bl   = (const float*)d_in[3];
    const float* Wr   = (const float*)d_in[4];
    const float* br   = (const float*)d_in[5];
    const float* att  = (const float*)d_in[6];
    const float* bias = (const float*)d_in[7];
    float*       out  = (float*)d_out;

    csr_gemm_kernel<<<NB_SCAN + NB_MMA, 256>>>(x, ei, Wl, bl, Wr, br);
    agg_kernel<<<(N_NODES * 32 + 255) / 256, 256>>>(att, bias, out);
}

// round 13
// speedup vs baseline: 2.2810x; 1.0698x over previous
#include <cuda_runtime.h>
#include <cuda_bf16.h>
#include <cstdint>

#define N_NODES 50000
#define N_EDGES 800000
#define CH 128          // HEADS*OUT_CH = 4*32
#define SCAN_B 256
#define NB_SCAN ((N_NODES + SCAN_B - 1) / SCAN_B)   // 196
#define N_TILES ((N_NODES + 127) / 128)              // 391
#define NB_MMA (N_TILES * 4)                         // 1564: tile x mat x nhalf

// ---------------- scratch (static device memory; zero-init at load) ----------
__device__ __align__(16) float g_xl[N_NODES * CH];
__device__ __align__(16) float g_xr[N_NODES * CH];
__device__ int g_cnt[N_NODES];        // zero-init; consumed+re-zeroed in-kernel
__device__ int g_off[N_NODES + 1];
__device__ int g_esrc[N_EDGES];
__device__ int g_bsum[NB_SCAN];
__device__ int g_sync0, g_sync1, g_sync2, g_sync3;   // self-resetting counters

// ---------------- helpers -----------------------------------------------------
__device__ __forceinline__ uint32_t smem_u32(const void* p) {
    uint32_t a;
    asm("{ .reg .u64 t; cvta.to.shared.u64 t, %1; cvt.u32.u64 %0, t; }"
        : "=r"(a) : "l"(p));
    return a;
}
// bf16 split of a float pair -> packed hi word + lo word
__device__ __forceinline__ void split2(float a, float b,
                                       uint32_t& hi, uint32_t& lo) {
    __nv_bfloat162 h = __floats2bfloat162_rn(a, b);
    float ra = a - __bfloat162float(h.x);
    float rb = b - __bfloat162float(h.y);
    __nv_bfloat162 l = __floats2bfloat162_rn(ra, rb);
    hi = *(uint32_t*)&h;
    lo = *(uint32_t*)&l;
}
__device__ __forceinline__ void ldsm_x4(uint32_t* r, uint32_t addr) {
    asm volatile("ldmatrix.sync.aligned.m8n8.x4.shared.b16 {%0,%1,%2,%3}, [%4];"
                 : "=r"(r[0]), "=r"(r[1]), "=r"(r[2]), "=r"(r[3]) : "r"(addr));
}
__device__ __forceinline__ void ldsm_x2(uint32_t* r, uint32_t addr) {
    asm volatile("ldmatrix.sync.aligned.m8n8.x2.shared.b16 {%0,%1}, [%2];"
                 : "=r"(r[0]), "=r"(r[1]) : "r"(addr));
}
__device__ __forceinline__ void mma16816(float* d, const uint32_t* a,
                                         const uint32_t* b) {
    asm volatile(
        "mma.sync.aligned.m16n8k16.row.col.f32.bf16.bf16.f32 "
        "{%0,%1,%2,%3}, {%4,%5,%6,%7}, {%8,%9}, {%0,%1,%2,%3};"
        : "+f"(d[0]), "+f"(d[1]), "+f"(d[2]), "+f"(d[3])
        : "r"(a[0]), "r"(a[1]), "r"(a[2]), "r"(a[3]), "r"(b[0]), "r"(b[1]));
}

// ---------------- K1: fused CSR build (196 blocks) + bf16x3 HMMA GEMM --------
#define PITCH 40
#define A_HL_OFF (128 * PITCH * 2)
#define W_HL_OFF (64 * PITCH * 2)

__global__ __launch_bounds__(256)
void csr_gemm_kernel(const float* __restrict__ X,
                     const int* __restrict__ ei,
                     const float* __restrict__ Wl, const float* __restrict__ bl,
                     const float* __restrict__ Wr, const float* __restrict__ br) {
    const int tid  = threadIdx.x;
    const int lane = tid & 31;

    if (blockIdx.x < NB_SCAN) {            // ================= CSR path =======
        __shared__ int ws[8];
        __shared__ int s_base;
        const int b   = blockIdx.x;
        const int wid = tid >> 5;

        for (int e = b * SCAN_B + tid; e < N_EDGES; e += NB_SCAN * SCAN_B)
            atomicAdd(&g_cnt[ei[N_EDGES + e]], 1);
        __threadfence();
        __syncthreads();
        if (tid == 0) {
            atomicAdd(&g_sync0, 1);
            while (*(volatile int*)&g_sync0 < NB_SCAN) {}
            __threadfence();
        }
        __syncthreads();

        int idx = b * SCAN_B + tid;
        int v = 0;
        if (idx < N_NODES) { v = g_cnt[idx]; g_cnt[idx] = 0; }
        int s = v;
#pragma unroll
        for (int o = 1; o < 32; o <<= 1) {
            int u = __shfl_up_sync(0xffffffffu, s, o);
            if (lane >= o) s += u;
        }
        if (lane == 31) ws[wid] = s;
        __syncthreads();
        if (wid == 0) {
            int t = (lane < 8) ? ws[lane] : 0;
#pragma unroll
            for (int o = 1; o < 8; o <<= 1) {
                int u = __shfl_up_sync(0xffffffffu, t, o, 8);
                if ((lane & 7) >= o) t += u;
            }
            if (lane < 8) ws[lane] = t;
        }
        __syncthreads();
        int blocksum   = ws[7];
        int local_excl = (wid ? ws[wid - 1] : 0) + s - v;
        __syncthreads();

        if (tid == 0) {
            g_bsum[b] = blocksum;
            __threadfence();
            atomicAdd(&g_sync1, 1);
            while (*(volatile int*)&g_sync1 < NB_SCAN) {}
            __threadfence();
        }
        __syncthreads();

        int pv = (tid < b) ? g_bsum[tid] : 0;
#pragma unroll
        for (int o = 16; o > 0; o >>= 1)
            pv += __shfl_xor_sync(0xffffffffu, pv, o);
        if (lane == 0) ws[wid] = pv;
        __syncthreads();
        if (tid == 0) {
            int tot = 0;
#pragma unroll
            for (int i = 0; i < 8; i++) tot += ws[i];
            s_base = tot;
        }
        __syncthreads();
        int base = s_base;

        if (idx < N_NODES) g_off[idx] = base + local_excl;
        if (b == NB_SCAN - 1 && tid == 0) g_off[N_NODES] = base + blocksum;

        if (tid == 0) {
            __threadfence();
            atomicAdd(&g_sync2, 1);
            while (*(volatile int*)&g_sync2 < NB_SCAN) {}
            __threadfence();
            int t3 = atomicAdd(&g_sync3, 1);
            if (t3 == NB_SCAN - 1) {
                g_sync0 = 0; g_sync1 = 0; g_sync2 = 0; g_sync3 = 0;
            }
        }
        __syncthreads();

        for (int e = b * SCAN_B + tid; e < N_EDGES; e += NB_SCAN * SCAN_B) {
            int sp = ei[e];
            int tg = ei[N_EDGES + e];
            int pos = atomicAdd(&g_off[tg], 1);
            g_esrc[pos] = sp;
        }
        return;
    }

    // ================= GEMM path =============================================
    __shared__ __align__(16) uint16_t As[2][128 * PITCH];
    __shared__ __align__(16) uint16_t Ws[2][64 * PITCH];

    const int gb   = blockIdx.x - NB_SCAN;
    const int tile = gb >> 2;
    const int mat  = (gb >> 1) & 1;
    const int nh   = gb & 1;
    const int nb   = tile * 128;
    const int o0   = nh * 64;
    const float* W    = mat ? Wr : Wl;
    const float* bias = mat ? br : bl;
    float* dst        = mat ? g_xr : g_xl;

    const int warp = tid >> 5;
    const int m_warp = (warp & 3) * 32;
    const int n_warp = (warp >> 2) * 32;

    const uint32_t as_base = smem_u32(As);
    const uint32_t ws_base = smem_u32(Ws);

    float acc[2][4][4];
#pragma unroll
    for (int mt = 0; mt < 2; mt++)
#pragma unroll
        for (int nt = 0; nt < 4; nt++)
#pragma unroll
            for (int q = 0; q < 4; q++) acc[mt][nt][q] = 0.f;

    const int arow = lane & 15;
    const int acol8 = (lane >> 4) << 3;
    const int brow = lane & 7;
    const int bcol8 = ((lane >> 3) & 1) << 3;

    for (int kt = 0; kt < CH; kt += 32) {
#pragma unroll
        for (int t = 0; t < 4; t++) {
            int idx = tid + t * 256;
            int row = idx >> 3;
            int kq  = (idx & 7) << 2;
            int gn  = nb + row;
            float4 v = make_float4(0.f, 0.f, 0.f, 0.f);
            if (gn < N_NODES) v = *(const float4*)(X + gn * CH + kt + kq);
            uint32_t h0, l0, h1, l1;
            split2(v.x, v.y, h0, l0);
            split2(v.z, v.w, h1, l1);
            int sw = (row * PITCH + kq) >> 1;
            ((uint32_t*)As[0])[sw]     = h0;
            ((uint32_t*)As[0])[sw + 1] = h1;
            ((uint32_t*)As[1])[sw]     = l0;
            ((uint32_t*)As[1])[sw + 1] = l1;
        }
#pragma unroll
        for (int t = 0; t < 2; t++) {
            int idx = tid + t * 256;
            int row = idx >> 3;
            int kq  = (idx & 7) << 2;
            float4 v = *(const float4*)(W + (o0 + row) * CH + kt + kq);
            uint32_t h0, l0, h1, l1;
            split2(v.x, v.y, h0, l0);
            split2(v.z, v.w, h1, l1);
            int sw = (row * PITCH + kq) >> 1;
            ((uint32_t*)Ws[0])[sw]     = h0;
            ((uint32_t*)Ws[0])[sw + 1] = h1;
            ((uint32_t*)Ws[1])[sw]     = l0;
            ((uint32_t*)Ws[1])[sw + 1] = l1;
        }
        __syncthreads();

#pragma unroll
        for (int ks = 0; ks < 32; ks += 16) {
            uint32_t ah[2][4], alo[2][4];
#pragma unroll
            for (int mt = 0; mt < 2; mt++) {
                uint32_t adr = as_base +
                    ((m_warp + mt * 16 + arow) * PITCH + ks + acol8) * 2;
                ldsm_x4(ah[mt], adr);
                ldsm_x4(alo[mt], adr + A_HL_OFF);
            }
            uint32_t bh[4][2], blo2[4][2];
#pragma unroll
            for (int nt = 0; nt < 4; nt++) {
                uint32_t adr = ws_base +
                    ((n_warp + nt * 8 + brow) * PITCH + ks + bcol8) * 2;
                ldsm_x2(bh[nt], adr);
                ldsm_x2(blo2[nt], adr + W_HL_OFF);
            }
#pragma unroll
            for (int mt = 0; mt < 2; mt++)
#pragma unroll
                for (int nt = 0; nt < 4; nt++) {
                    mma16816(acc[mt][nt], ah[mt], bh[nt]);
                    mma16816(acc[mt][nt], ah[mt], blo2[nt]);
                    mma16816(acc[mt][nt], alo[mt], bh[nt]);
                }
        }
        __syncthreads();
    }

    const int r0 = lane >> 2;
    const int c0 = (lane & 3) << 1;
#pragma unroll
    for (int mt = 0; mt < 2; mt++) {
        int m0 = nb + m_warp + mt * 16 + r0;
#pragma unroll
        for (int nt = 0; nt < 4; nt++) {
            int o = o0 + n_warp + nt * 8 + c0;
            float b0 = __ldg(&bias[o]);
            float b1 = __ldg(&bias[o + 1]);
            if (m0 < N_NODES) {
                float2 r = make_float2(acc[mt][nt][0] + b0, acc[mt][nt][1] + b1);
                *(float2*)(dst + m0 * CH + o) = r;
            }
            if (m0 + 8 < N_NODES) {
                float2 r = make_float2(acc[mt][nt][2] + b0, acc[mt][nt][3] + b1);
                *(float2*)(dst + (m0 + 8) * CH + o) = r;
            }
        }
    }
}

// ---------------- K2: warp-per-node online-softmax, 4-edge batched -----------
// leaky(s) = 0.6s + 0.4|s| (NEG_SLOPE=0.2), folded into scaled att vectors.
// 4-edge batch keeps xv[] at 16 regs -> ~50% occupancy (the 8-edge version's
// 80 regs collapsed occupancy to 29% and LOST time).
__global__ __launch_bounds__(256, 4)
void agg_kernel(const float* __restrict__ att,
                const float* __restrict__ bias,
                float* __restrict__ out) {
    int w    = (blockIdx.x * blockDim.x + threadIdx.x) >> 5;
    int lane = threadIdx.x & 31;
    if (w >= N_NODES) return;
    const int i  = w;
    const int c0 = lane << 2;

    const float4 xlv = *(const float4*)(g_xl + i * CH + c0);
    const float4 av  = *(const float4*)(att + c0);
    const float4 xrs = *(const float4*)(g_xr + i * CH + c0);
    const float4 a6 = make_float4(0.6f * av.x, 0.6f * av.y,
                                  0.6f * av.z, 0.6f * av.w);
    const float4 a4 = make_float4(0.4f * av.x, 0.4f * av.y,
                                  0.4f * av.z, 0.4f * av.w);

    float s0 = xlv.x + xrs.x, s1 = xlv.y + xrs.y;
    float s2 = xlv.z + xrs.z, s3 = xlv.w + xrs.w;
    float p = a6.x * s0 + a4.x * fabsf(s0);
    p += a6.y * s1 + a4.y * fabsf(s1);
    p += a6.z * s2 + a4.z * fabsf(s2);
    p += a6.w * s3 + a4.w * fabsf(s3);
#pragma unroll
    for (int o = 1; o < 8; o <<= 1) p += __shfl_xor_sync(0xffffffffu, p, o);

    float m = p;
    float d = 1.0f;
    float4 acc = xrs;

    int e = i ? __ldg(&g_off[i - 1]) : 0;
    const int end = __ldg(&g_off[i]);

    // ---- 4-edge batches ----
    for (; e + 4 <= end; e += 4) {
        float4 xv[4];
#pragma unroll
        for (int j = 0; j < 4; j++) {
            int src = __ldg(&g_esrc[e + j]);
            xv[j] = *(const float4*)(g_xr + src * CH + c0);
        }
        float pj[4];
#pragma unroll
        for (int j = 0; j < 4; j++) {
            float t0 = xlv.x + xv[j].x;
            float t1 = xlv.y + xv[j].y;
            float t2 = xlv.z + xv[j].z;
            float t3 = xlv.w + xv[j].w;
            float q = a6.x * t0 + a4.x * fabsf(t0);
            q += a6.y * t1 + a4.y * fabsf(t1);
            q += a6.z * t2 + a4.z * fabsf(t2);
            q += a6.w * t3 + a4.w * fabsf(t3);
            pj[j] = q;
        }
        // butterfly transpose: after xor1+xor2, lane l holds edge (l&3) summed
        // over its 4-lane subgroup; xor4 add completes the 8-lane head sum.
        {
            bool b0 = lane & 1;
#pragma unroll
            for (int k = 0; k < 2; k++) {
                float snd = b0 ? pj[2 * k] : pj[2 * k + 1];
                float kp  = b0 ? pj[2 * k + 1] : pj[2 * k];
                pj[k] = kp + __shfl_xor_sync(0xffffffffu, snd, 1);
            }
            bool b1 = lane & 2;
            {
                float snd = b1 ? pj[0] : pj[1];
                float kp  = b1 ? pj[1] : pj[0];
                pj[0] = kp + __shfl_xor_sync(0xffffffffu, snd, 2);
            }
            pj[0] += __shfl_xor_sync(0xffffffffu, pj[0], 4);
        }
        float q = pj[0];                  // edge (lane&3) logit, dup at xor4
        float qm = fmaxf(q, __shfl_xor_sync(0xffffffffu, q, 1));
        qm = fmaxf(qm, __shfl_xor_sync(0xffffffffu, qm, 2));
        float nm = fmaxf(m, qm);
        float wq = __expf(q - nm);
        float wm = __expf(m - nm);
        m = nm;
        float wv[4];
        int gbase = lane & 24;
#pragma unroll
        for (int j = 0; j < 4; j++)
            wv[j] = __shfl_sync(0xffffffffu, wq, gbase + j);
        float dsum = (wv[0] + wv[1]) + (wv[2] + wv[3]);
        d = d * wm + dsum;
        acc.x *= wm; acc.y *= wm; acc.z *= wm; acc.w *= wm;
#pragma unroll
        for (int j = 0; j < 4; j++) {
            acc.x += wv[j] * xv[j].x;
            acc.y += wv[j] * xv[j].y;
            acc.z += wv[j] * xv[j].z;
            acc.w += wv[j] * xv[j].w;
        }
    }

    // ---- remainder ----
    for (; e < end; e++) {
        int src = __ldg(&g_esrc[e]);
        float4 xv = *(const float4*)(g_xr + src * CH + c0);
        float t0 = xlv.x + xv.x;
        float t1 = xlv.y + xv.y;
        float t2 = xlv.z + xv.z;
        float t3 = xlv.w + xv.w;
        float q = a6.x * t0 + a4.x * fabsf(t0);
        q += a6.y * t1 + a4.y * fabsf(t1);
        q += a6.z * t2 + a4.z * fabsf(t2);
        q += a6.w * t3 + a4.w * fabsf(t3);
#pragma unroll
        for (int o = 1; o < 8; o <<= 1)
            q += __shfl_xor_sync(0xffffffffu, q, o);

        float nm = fmaxf(m, q);
        float wm = __expf(m - nm);
        float wq = __expf(q - nm);
        d = d * wm + wq;
        acc.x = acc.x * wm + wq * xv.x;
        acc.y = acc.y * wm + wq * xv.y;
        acc.z = acc.z * wm + wq * xv.z;
        acc.w = acc.w * wm + wq * xv.w;
        m = nm;
    }

    float inv = 1.0f / d;
    const float4 bv = *(const float4*)(bias + c0);
    float4 r = make_float4(acc.x * inv + bv.x, acc.y * inv + bv.y,
                           acc.z * inv + bv.z, acc.w * inv + bv.w);
    *(float4*)(out + i * CH + c0) = r;
}

// ---------------- launch ------------------------------------------------------
extern "C" void kernel_launch(void* const* d_in, const int* in_sizes, int n_in,
                              void* d_out, int out_size) {
    const float* x    = (const float*)d_in[0];
    const int*   ei   = (const int*)d_in[1];     // int32 (JAX x64 disabled)
    const float* Wl   = (const float*)d_in[2];
    const float* bl   = (const float*)d_in[3];
    const float* Wr   = (const float*)d_in[4];
    const float* br   = (const float*)d_in[5];
    const float* att  = (const float*)d_in[6];
    const float* bias = (const float*)d_in[7];
    float*       out  = (float*)d_out;

    csr_gemm_kernel<<<NB_SCAN + NB_MMA, 256>>>(x, ei, Wl, bl, Wr, br);
    agg_kernel<<<(N_NODES * 32 + 255) / 256, 256>>>(att, bias, out);
}